// round 8
// baseline (speedup 1.0000x reference)
#include <cuda_runtime.h>
#include <math.h>
#include <cstdint>

#define BB 8
#define NN 8192
#define SS 1024
#define KK 64

// output layout (float32): new_xyz (B,3,S) | new_points (B,128,S) | new_seed (B,S)
#define OUT_XYZ_OFF   0
#define OUT_PTS_OFF   (BB*3*SS)                 // 24576
#define OUT_SEED_OFF  (OUT_PTS_OFF + BB*128*SS) // 1073152

// ---------------- scratch (no allocations allowed) ----------------
__device__ float g_cent[BB*SS*3];
__device__ int   g_gi[BB*SS*KK];
__device__ int   g_cnt[BB*SS];
__device__ float g_w0[64*6],   g_b0[64];
__device__ float g_w1t[64*64], g_b1[64];    // w1t[cc*64 + c] = w1[c][cc] * s1(c)
__device__ float g_w2t[64*128], g_b2[128];  // w2t[cc*128 + o] = w2[o][cc] * s2(o)

// ---------------- f32x2 packed helpers (exact per-lane rn rounding) ----------------
__device__ __forceinline__ unsigned long long f2pack(float lo, float hi) {
    unsigned long long r;
    asm("mov.b64 %0, {%1, %2};" : "=l"(r) : "f"(lo), "f"(hi));
    return r;
}
__device__ __forceinline__ void f2unpack(unsigned long long v, float& lo, float& hi) {
    asm("mov.b64 {%0, %1}, %2;" : "=f"(lo), "=f"(hi) : "l"(v));
}
__device__ __forceinline__ unsigned long long f2add(unsigned long long a, unsigned long long b) {
    unsigned long long d;
    asm("add.rn.f32x2 %0, %1, %2;" : "=l"(d) : "l"(a), "l"(b));
    return d;
}
__device__ __forceinline__ unsigned long long f2mul(unsigned long long a, unsigned long long b) {
    unsigned long long d;
    asm("mul.rn.f32x2 %0, %1, %2;" : "=l"(d) : "l"(a), "l"(b));
    return d;
}

// ---------------- cluster helpers (DSMEM mailbox, proven in R5/R7) ----------------
__device__ __forceinline__ uint32_t smem_u32(const void* p) {
    uint32_t a;
    asm("{ .reg .u64 t; cvta.to.shared.u64 t, %1; cvt.u32.u64 %0, t; }" : "=r"(a) : "l"(p));
    return a;
}
__device__ __forceinline__ uint32_t mapa_u32(uint32_t addr, uint32_t rank) {
    uint32_t r; asm("mapa.shared::cluster.u32 %0, %1, %2;" : "=r"(r) : "r"(addr), "r"(rank));
    return r;
}
__device__ __forceinline__ void st_cluster_u64(uint32_t addr, unsigned long long v) {
    asm volatile("st.relaxed.cluster.shared::cluster.u64 [%0], %1;" :: "r"(addr), "l"(v) : "memory");
}
__device__ __forceinline__ unsigned long long ld_cta_u64(uint32_t addr) {
    unsigned long long v;
    asm volatile("ld.relaxed.cluster.shared::cta.u64 %0, [%1];" : "=l"(v) : "r"(addr) : "memory");
    return v;
}

// ---------------- fold BN into weights (+ transpose for mlp) ----------------
__global__ void fold_kernel(
    const float* __restrict__ w0, const float* __restrict__ b0, const float* __restrict__ g0,
    const float* __restrict__ be0, const float* __restrict__ m0, const float* __restrict__ v0,
    const float* __restrict__ w1, const float* __restrict__ b1, const float* __restrict__ g1,
    const float* __restrict__ be1, const float* __restrict__ m1, const float* __restrict__ v1,
    const float* __restrict__ w2, const float* __restrict__ b2, const float* __restrict__ g2,
    const float* __restrict__ be2, const float* __restrict__ m2, const float* __restrict__ v2)
{
    int t = threadIdx.x;
    if (t < 64) {
        float s = g0[t] / sqrtf(v0[t] + 1e-5f);
        g_b0[t] = (b0[t] - m0[t]) * s + be0[t];
        for (int c = 0; c < 6; c++) g_w0[t*6+c] = w0[t*6+c] * s;
    }
    if (t < 64) {
        float s = g1[t] / sqrtf(v1[t] + 1e-5f);
        g_b1[t] = (b1[t] - m1[t]) * s + be1[t];
        for (int cc = 0; cc < 64; cc++) g_w1t[cc*64 + t] = w1[t*64+cc] * s;
    }
    if (t < 128) {
        float s = g2[t] / sqrtf(v2[t] + 1e-5f);
        g_b2[t] = (b2[t] - m2[t]) * s + be2[t];
        for (int cc = 0; cc < 64; cc++) g_w2t[cc*128 + t] = w2[t*64+cc] * s;
    }
}

// ---------------- FPS: 4-CTA cluster per batch, 2 points/thread ----------------
// Exact reference arithmetic: packed add.rn/mul.rn.f32x2 (per-lane rounding ==
// scalar rn) in the reference association order ((dx2+dy2)+dz2).
// Per iteration (ONE __syncthreads):
//   update 2 pts -> warp argmax via redux/select/redux (no ballot/shfl) ->
//   leaders STS skey[par][warp] -> bar -> every warp reduces the 32 keys ->
//   tids 0..2 send CTA best to the 3 peers in PARALLEL (phase-tagged u64) ->
//   every warp polls its 3 local mailbox slots -> combine 4 keys -> far.
// Double-buffered skey/mbox (parity s&1, phase (s>>1)&1): slot reuse at s+2 is
// ordered behind the sender's s+1 chain which transitively requires our s poll
// — race-free (same argument as the proven 2-CTA version).
// Keys are (distbits<<32 | 8191-idx): u64 max == (max dist, min index) == jnp.argmax.
__global__ __launch_bounds__(1024) __cluster_dims__(4, 1, 1)
void fps_kernel(const float* __restrict__ xyz, const int* __restrict__ seed,
                float* __restrict__ out)
{
    const int b = blockIdx.x >> 2;
    const uint32_t rank = blockIdx.x & 3;
    const float* xr = xyz + (size_t)b*3*NN;
    const float* yr = xr + NN;
    const float* zr = yr + NN;
    const int tid = threadIdx.x, lane = tid & 31, warp = tid >> 5;
    const int base = (int)rank * 2048 + tid * 2;   // this thread's 2 points

    extern __shared__ float fsm[];                 // full xyz copy (96KB)
    float* sx = fsm;
    float* sy = fsm + NN;
    float* sz = fsm + 2*NN;
    __shared__ unsigned long long skey[2][32];
    __shared__ unsigned long long mbox[2][4];      // [parity][source rank]
    __shared__ int sfps[SS];

    // smem copy of full xyz — centroid lookups hit LDS
    {
        const float4* x4 = (const float4*)xr;
        const float4* y4 = (const float4*)yr;
        const float4* z4 = (const float4*)zr;
#pragma unroll
        for (int i = 0; i < 2; i++) {
            ((float4*)sx)[tid + i*1024] = x4[tid + i*1024];
            ((float4*)sy)[tid + i*1024] = y4[tid + i*1024];
            ((float4*)sz)[tid + i*1024] = z4[tid + i*1024];
        }
    }
    // own 2 points packed
    unsigned long long pxp, pyp, pzp;
    float dist0 = 1e10f, dist1 = 1e10f;
    {
        float2 vx = ((const float2*)xr)[base/2];
        float2 vy = ((const float2*)yr)[base/2];
        float2 vz = ((const float2*)zr)[base/2];
        pxp = f2pack(vx.x, vx.y);
        pyp = f2pack(vy.x, vy.y);
        pzp = f2pack(vz.x, vz.y);
    }
    if (tid < 8) ((unsigned long long*)mbox)[tid] = 0x80000000ULL;  // wrong phase
    __syncthreads();
    asm volatile("barrier.cluster.arrive.aligned;" ::: "memory");
    asm volatile("barrier.cluster.wait.aligned;"   ::: "memory");

    const uint32_t mb_base = smem_u32(&mbox[0][0]);
    // the three peer ranks (compile-time-ish constants per CTA)
    const uint32_t pr0 = (rank + 1) & 3;
    const uint32_t pr1 = (rank + 2) & 3;
    const uint32_t pr2 = (rank + 3) & 3;

    int far = 0;
    for (int s = 0; s < SS; s++) {
        if (rank == 0 && tid == 0) sfps[s] = far;
        if (s == SS - 1) break;
        const int par = s & 1;
        const unsigned ph = (unsigned)((s >> 1) & 1);

        const float cx = sx[far], cy = sy[far], cz = sz[far];
        unsigned long long ncx2 = f2pack(-cx, -cx);
        unsigned long long ncy2 = f2pack(-cy, -cy);
        unsigned long long ncz2 = f2pack(-cz, -cz);

        // update 2 points (exact ref association order)
        {
            unsigned long long dx = f2add(pxp, ncx2);
            unsigned long long dy = f2add(pyp, ncy2);
            unsigned long long dz = f2add(pzp, ncz2);
            unsigned long long d  = f2add(f2add(f2mul(dx,dx), f2mul(dy,dy)), f2mul(dz,dz));
            float dlo, dhi; f2unpack(d, dlo, dhi);
            dist0 = fminf(dist0, dlo);
            dist1 = fminf(dist1, dhi);
        }
        float bv; int bi;
        if (dist1 > dist0) { bv = dist1; bi = base + 1; }
        else               { bv = dist0; bi = base; }

        // warp argmax: redux -> select -> redux (2 dependent redux, no shfl)
        unsigned vb = __float_as_uint(bv);
        unsigned mv = __reduce_max_sync(0xffffffffu, vb);
        unsigned cand = (vb == mv) ? (unsigned)(8191 - bi) : 0u;
        unsigned ml = __reduce_max_sync(0xffffffffu, cand);
        if (lane == 0)
            skey[par][warp] = ((unsigned long long)mv << 32) | ml;
        __syncthreads();

        // every warp redundantly reduces the 32 leader keys
        unsigned long long k = skey[par][lane];
        unsigned hi = (unsigned)(k >> 32), lo = (unsigned)k;
        unsigned mh  = __reduce_max_sync(0xffffffffu, hi);
        unsigned loe = (hi == mh) ? lo : 0u;
        unsigned mll = __reduce_max_sync(0xffffffffu, loe);
        unsigned long long lk = ((unsigned long long)mh << 32) | mll;

        // tids 0..2 send CTA best to the 3 peers in parallel
        if (tid < 3) {
            uint32_t peer = (tid == 0) ? pr0 : (tid == 1) ? pr1 : pr2;
            uint32_t dst = mapa_u32(mb_base + (uint32_t)par * 32u + rank * 8u, peer);
            st_cluster_u64(dst, lk | ((unsigned long long)ph << 31));
        }

        // poll the 3 peer slots (first poll absorbs transit; rest hit)
        unsigned long long best = lk;
#pragma unroll
        for (int i = 0; i < 3; i++) {
            uint32_t c = (i == 0) ? pr0 : (i == 1) ? pr1 : pr2;
            uint32_t a = mb_base + (uint32_t)par * 32u + c * 8u;
            unsigned long long rk;
            do { rk = ld_cta_u64(a); } while ((((unsigned)(rk >> 31)) & 1u) != ph);
            rk &= ~(1ULL << 31);
            if (rk > best) best = rk;
        }
        far = 8191 - (int)((unsigned)best & 8191u);
    }
    __syncthreads();

    if (rank == 0) {
        int id = sfps[tid];
        float x = sx[id], y = sy[id], z = sz[id];
        out[OUT_XYZ_OFF + (size_t)b*3*SS + 0*SS + tid] = x;
        out[OUT_XYZ_OFF + (size_t)b*3*SS + 1*SS + tid] = y;
        out[OUT_XYZ_OFF + (size_t)b*3*SS + 2*SS + tid] = z;
        out[OUT_SEED_OFF + (size_t)b*SS + tid] = (float)seed[(size_t)b*NN + id];
        g_cent[((size_t)b*SS + tid)*3 + 0] = x;
        g_cent[((size_t)b*SS + tid)*3 + 1] = y;
        g_cent[((size_t)b*SS + tid)*3 + 2] = z;
    }

    asm volatile("barrier.cluster.arrive.aligned;" ::: "memory");
    asm volatile("barrier.cluster.wait.aligned;"   ::: "memory");
}

// ---------------- ball query: warp per centroid, 2 points/thread -------------
// Exact per-point reference math. Dual-ballot rank preserves index order.
__global__ __launch_bounds__(256) void ballq_kernel(const float* __restrict__ xyz)
{
    const int gw = blockIdx.x * 8 + (threadIdx.x >> 5);
    const int lane = threadIdx.x & 31;
    const int b = gw >> 10;
    const int s = gw & 1023;
    const float* xr = xyz + (size_t)b*3*NN;
    const float* yr = xr + NN;
    const float* zr = yr + NN;

    const float cx = g_cent[((size_t)b*SS+s)*3+0];
    const float cy = g_cent[((size_t)b*SS+s)*3+1];
    const float cz = g_cent[((size_t)b*SS+s)*3+2];
    const float s2 = __fadd_rn(__fadd_rn(__fmul_rn(cx,cx), __fmul_rn(cy,cy)), __fmul_rn(cz,cz));

    __shared__ int sgi[8][KK];
    int* mygi = sgi[threadIdx.x >> 5];

    int cnt = 0;
    const unsigned below = (1u << lane) - 1u;
    for (int j0 = 0; j0 < NN; j0 += 64) {
        int j = j0 + 2*lane;
        float2 xv = *(const float2*)&xr[j];
        float2 yv = *(const float2*)&yr[j];
        float2 zv = *(const float2*)&zr[j];

        float d2a  = __fadd_rn(__fadd_rn(__fmul_rn(xv.x,xv.x), __fmul_rn(yv.x,yv.x)), __fmul_rn(zv.x,zv.x));
        float dota = __fadd_rn(__fadd_rn(__fmul_rn(cx,xv.x),  __fmul_rn(cy,yv.x)),  __fmul_rn(cz,zv.x));
        float sqa  = __fadd_rn(__fadd_rn(__fmul_rn(-2.0f, dota), s2), d2a);
        float d2b  = __fadd_rn(__fadd_rn(__fmul_rn(xv.y,xv.y), __fmul_rn(yv.y,yv.y)), __fmul_rn(zv.y,zv.y));
        float dotb = __fadd_rn(__fadd_rn(__fmul_rn(cx,xv.y),  __fmul_rn(cy,yv.y)),  __fmul_rn(cz,zv.y));
        float sqb  = __fadd_rn(__fadd_rn(__fmul_rn(-2.0f, dotb), s2), d2b);

        int pa = !(sqa > 0.04f);
        int pb = !(sqb > 0.04f);
        unsigned mA = __ballot_sync(0xffffffffu, pa);
        unsigned mB = __ballot_sync(0xffffffffu, pb);
        int rA = __popc(mA & below) + __popc(mB & below);
        int rB = rA + pa;
        if (pa && (cnt + rA) < KK) mygi[cnt + rA] = j;
        if (pb && (cnt + rB) < KK) mygi[cnt + rB] = j + 1;
        cnt += __popc(mA) + __popc(mB);
        if (cnt >= KK) { cnt = KK; break; }
    }
    __syncwarp();
    if (lane == 0) g_cnt[(size_t)b*SS + s] = cnt;
    for (int k = lane; k < cnt; k += 32)
        g_gi[((size_t)b*SS + s)*KK + k] = mygi[k];
}

// ---------------- fused gather + 3-layer MLP + maxpool (proven width-2) -------
#define MW 8   // warps (centroids) per block
#define O_W1T   0
#define O_W2T   4096
#define O_B1    12288
#define O_B2    12352
#define O_GFT   12480                   // MW * 384
#define O_H1    (O_GFT + MW*384)        // MW * 128 (2 neighbors x 64)
#define O_H2    (O_H1  + MW*128)        // MW * 128
#define O_SOUT  (O_H2  + MW*128)        // MW * 128
#define SMEMF   (O_SOUT + MW*128)

__global__ __launch_bounds__(32*MW) void mlp_kernel(
    const float* __restrict__ xyz, const float* __restrict__ pts, float* __restrict__ out)
{
    extern __shared__ float sm[];
    float* sw1t = sm + O_W1T;
    float* sw2t = sm + O_W2T;
    float* sb1  = sm + O_B1;
    float* sb2  = sm + O_B2;

    const int tid = threadIdx.x;
    {
        const float4* s1 = (const float4*)g_w1t;
        float4* d1 = (float4*)sw1t;
        for (int i = tid; i < 1024; i += 32*MW) d1[i] = s1[i];
        const float4* s2 = (const float4*)g_w2t;
        float4* d2 = (float4*)sw2t;
        for (int i = tid; i < 2048; i += 32*MW) d2[i] = s2[i];
        for (int i = tid; i < 64;  i += 32*MW) sb1[i] = g_b1[i];
        for (int i = tid; i < 128; i += 32*MW) sb2[i] = g_b2[i];
    }
    __syncthreads();

    const int w = tid >> 5;
    const int lane = tid & 31;
    const int gs = blockIdx.x * MW + w;          // global centroid id
    const int b = gs >> 10;
    const int cnt = g_cnt[gs];

    float* gft   = sm + O_GFT + w*384;
    float* h1row = sm + O_H1  + w*128;
    float* h2row = sm + O_H2  + w*128;
    float* sout  = sm + O_SOUT + w*128;

    const float cx = g_cent[(size_t)gs*3+0];
    const float cy = g_cent[(size_t)gs*3+1];
    const float cz = g_cent[(size_t)gs*3+2];

    // gather neighbor features up front
    {
        const int* gi = g_gi + (size_t)gs*KK;
        for (int t = lane; t < cnt*6; t += 32) {
            int k = t / 6, i = t - 6*k;
            int idx = gi[k];
            float v;
            if (i < 3) v = xyz[((size_t)b*3 + i)*NN + idx] - (i==0 ? cx : (i==1 ? cy : cz));
            else       v = pts[((size_t)b*3 + (i-3))*NN + idx];
            gft[t] = v;
        }
        if (cnt < KK && lane < 6) gft[cnt*6 + lane] = 0.0f;  // pad slot for odd cnt
    }

    const int cA = lane, cB = lane + 32;
    float w0A[6], w0B[6];
#pragma unroll
    for (int i = 0; i < 6; i++) { w0A[i] = g_w0[cA*6+i]; w0B[i] = g_w0[cB*6+i]; }
    const float b0A = g_b0[cA], b0B = g_b0[cB];
    const float b1A = sb1[cA],  b1B = sb1[cB];
    const float4 b2v = *(const float4*)&sb2[4*lane];

    float m0 = 0.f, m1 = 0.f, m2 = 0.f, m3 = 0.f;
    __syncwarp();

    for (int k = 0; k < cnt; k += 2) {
        // ---- layer 1, neighbors A=k, B=k+1 ----
        const float* fA = gft + k*6;
        const float* fB = fA + 6;
        {
            float a0 = b0A, a1 = b0B, a2 = b0A, a3 = b0B;
#pragma unroll
            for (int i = 0; i < 6; i++) {
                a0 += w0A[i]*fA[i]; a1 += w0B[i]*fA[i];
                a2 += w0A[i]*fB[i]; a3 += w0B[i]*fB[i];
            }
            h1row[cA]    = fmaxf(a0, 0.f);
            h1row[cB]    = fmaxf(a1, 0.f);
            h1row[64+cA] = fmaxf(a2, 0.f);
            h1row[64+cB] = fmaxf(a3, 0.f);
        }
        __syncwarp();

        // ---- layer 2 (weight loads shared between the 2 neighbors) ----
        float pA0 = b1A, pB0 = b1B, pA1 = b1A, pB1 = b1B;
        {
            const float4* hv = (const float4*)h1row;
#pragma unroll
            for (int c4 = 0; c4 < 16; c4++) {
                float4 ha = hv[c4];
                float4 hb = hv[16 + c4];
                const float* w1r = sw1t + c4*256;
                float a0 = w1r[cA],     a1 = w1r[64+cA], a2 = w1r[128+cA], a3 = w1r[192+cA];
                float bq0 = w1r[cB],    bq1 = w1r[64+cB], bq2 = w1r[128+cB], bq3 = w1r[192+cB];
                pA0 += a0*ha.x + a1*ha.y + a2*ha.z + a3*ha.w;
                pB0 += bq0*ha.x + bq1*ha.y + bq2*ha.z + bq3*ha.w;
                pA1 += a0*hb.x + a1*hb.y + a2*hb.z + a3*hb.w;
                pB1 += bq0*hb.x + bq1*hb.y + bq2*hb.z + bq3*hb.w;
            }
        }
        h2row[cA]    = fmaxf(pA0, 0.f);
        h2row[cB]    = fmaxf(pB0, 0.f);
        h2row[64+cA] = fmaxf(pA1, 0.f);
        h2row[64+cB] = fmaxf(pB1, 0.f);
        __syncwarp();

        // ---- layer 3 + running max (weight loads shared) ----
        float qa0=0.f,qa1=0.f,qa2=0.f,qa3=0.f;
        float qb0=0.f,qb1=0.f,qb2=0.f,qb3=0.f;
        {
            const float4* h2v = (const float4*)h2row;
#pragma unroll
            for (int c4 = 0; c4 < 16; c4++) {
                float4 ha = h2v[c4];
                float4 hb = h2v[16 + c4];
                const float* w2r = sw2t + c4*512;
                float4 wa = *(const float4*)(w2r +        4*lane);
                qa0 += wa.x*ha.x; qa1 += wa.y*ha.x; qa2 += wa.z*ha.x; qa3 += wa.w*ha.x;
                qb0 += wa.x*hb.x; qb1 += wa.y*hb.x; qb2 += wa.z*hb.x; qb3 += wa.w*hb.x;
                float4 wb = *(const float4*)(w2r + 128 + 4*lane);
                qa0 += wb.x*ha.y; qa1 += wb.y*ha.y; qa2 += wb.z*ha.y; qa3 += wb.w*ha.y;
                qb0 += wb.x*hb.y; qb1 += wb.y*hb.y; qb2 += wb.z*hb.y; qb3 += wb.w*hb.y;
                float4 wc = *(const float4*)(w2r + 256 + 4*lane);
                qa0 += wc.x*ha.z; qa1 += wc.y*ha.z; qa2 += wc.z*ha.z; qa3 += wc.w*ha.z;
                qb0 += wc.x*hb.z; qb1 += wc.y*hb.z; qb2 += wc.z*hb.z; qb3 += wc.w*hb.z;
                float4 wd = *(const float4*)(w2r + 384 + 4*lane);
                qa0 += wd.x*ha.w; qa1 += wd.y*ha.w; qa2 += wd.z*ha.w; qa3 += wd.w*ha.w;
                qb0 += wd.x*hb.w; qb1 += wd.y*hb.w; qb2 += wd.z*hb.w; qb3 += wd.w*hb.w;
            }
        }
        m0 = fmaxf(m0, fmaxf(b2v.x + qa0, 0.f));
        m1 = fmaxf(m1, fmaxf(b2v.y + qa1, 0.f));
        m2 = fmaxf(m2, fmaxf(b2v.z + qa2, 0.f));
        m3 = fmaxf(m3, fmaxf(b2v.w + qa3, 0.f));
        if (k + 1 < cnt) {  // neighbor B valid
            m0 = fmaxf(m0, fmaxf(b2v.x + qb0, 0.f));
            m1 = fmaxf(m1, fmaxf(b2v.y + qb1, 0.f));
            m2 = fmaxf(m2, fmaxf(b2v.z + qb2, 0.f));
            m3 = fmaxf(m3, fmaxf(b2v.w + qb3, 0.f));
        }
        __syncwarp();
    }

    sout[4*lane+0] = m0;
    sout[4*lane+1] = m1;
    sout[4*lane+2] = m2;
    sout[4*lane+3] = m3;
    __syncthreads();

    // coalesced output: 256 threads cover 8 centroids x 128 channels
    {
        int o  = tid & 127;
        int c2 = tid >> 7;                       // 0 or 1 -> centroids c2*4..c2*4+3
        int bb = blockIdx.x >> 7;                // 128 blocks per batch
        int s0 = (blockIdx.x & 127) * MW + c2*4;
        float4 v;
        v.x = sm[O_SOUT + (c2*4+0)*128 + o];
        v.y = sm[O_SOUT + (c2*4+1)*128 + o];
        v.z = sm[O_SOUT + (c2*4+2)*128 + o];
        v.w = sm[O_SOUT + (c2*4+3)*128 + o];
        *(float4*)&out[OUT_PTS_OFF + ((size_t)bb*128 + o)*SS + s0] = v;
    }
}

// ---------------- launch ----------------
extern "C" void kernel_launch(void* const* d_in, const int* in_sizes, int n_in,
                              void* d_out, int out_size)
{
    const float* xyz  = (const float*)d_in[0];
    const float* pts  = (const float*)d_in[1];
    const int*   seed = (const int*)d_in[2];
    float* out = (float*)d_out;

    fold_kernel<<<1, 128>>>(
        (const float*)d_in[3],  (const float*)d_in[4],  (const float*)d_in[5],
        (const float*)d_in[6],  (const float*)d_in[7],  (const float*)d_in[8],
        (const float*)d_in[9],  (const float*)d_in[10], (const float*)d_in[11],
        (const float*)d_in[12], (const float*)d_in[13], (const float*)d_in[14],
        (const float*)d_in[15], (const float*)d_in[16], (const float*)d_in[17],
        (const float*)d_in[18], (const float*)d_in[19], (const float*)d_in[20]);

    cudaFuncSetAttribute(fps_kernel, cudaFuncAttributeMaxDynamicSharedMemorySize,
                         3*NN*sizeof(float));
    fps_kernel<<<BB*4, 1024, 3*NN*sizeof(float)>>>(xyz, seed, out);

    ballq_kernel<<<(BB*SS)/8, 256>>>(xyz);

    cudaFuncSetAttribute(mlp_kernel, cudaFuncAttributeMaxDynamicSharedMemorySize,
                         SMEMF * sizeof(float));
    mlp_kernel<<<(BB*SS)/MW, 32*MW, SMEMF * sizeof(float)>>>(xyz, pts, out);
}

// round 9
// speedup vs baseline: 1.0277x; 1.0277x over previous
#include <cuda_runtime.h>
#include <math.h>
#include <cstdint>

#define BB 8
#define NN 8192
#define SS 1024
#define KK 64

// output layout (float32): new_xyz (B,3,S) | new_points (B,128,S) | new_seed (B,S)
#define OUT_XYZ_OFF   0
#define OUT_PTS_OFF   (BB*3*SS)                 // 24576
#define OUT_SEED_OFF  (OUT_PTS_OFF + BB*128*SS) // 1073152

// ---------------- scratch (no allocations allowed) ----------------
__device__ float g_cent[BB*SS*3];
__device__ int   g_gi[BB*SS*KK];
__device__ int   g_cnt[BB*SS];
__device__ int   g_bcnt[65];       // histogram of cnt (zeroed by fold each launch)
__device__ int   g_boff[65];       // exclusive prefix
__device__ int   g_rank[BB*SS];    // rank within bucket
__device__ int   g_perm[BB*SS];    // centroids sorted by cnt
__device__ float g_w0[64*6],   g_b0[64];
__device__ float g_w1t[64*64], g_b1[64];    // w1t[cc*64 + c] = w1[c][cc] * s1(c)
__device__ float g_w2t[64*128], g_b2[128];  // w2t[cc*128 + o] = w2[o][cc] * s2(o)

// ---------------- f32x2 packed helpers (exact per-lane rn rounding) ----------------
__device__ __forceinline__ unsigned long long f2pack(float lo, float hi) {
    unsigned long long r;
    asm("mov.b64 %0, {%1, %2};" : "=l"(r) : "f"(lo), "f"(hi));
    return r;
}
__device__ __forceinline__ void f2unpack(unsigned long long v, float& lo, float& hi) {
    asm("mov.b64 {%0, %1}, %2;" : "=f"(lo), "=f"(hi) : "l"(v));
}
__device__ __forceinline__ unsigned long long f2add(unsigned long long a, unsigned long long b) {
    unsigned long long d;
    asm("add.rn.f32x2 %0, %1, %2;" : "=l"(d) : "l"(a), "l"(b));
    return d;
}
__device__ __forceinline__ unsigned long long f2mul(unsigned long long a, unsigned long long b) {
    unsigned long long d;
    asm("mul.rn.f32x2 %0, %1, %2;" : "=l"(d) : "l"(a), "l"(b));
    return d;
}

// ---------------- cluster helpers (DSMEM, proven in R5/R7) ----------------
__device__ __forceinline__ uint32_t smem_u32(const void* p) {
    uint32_t a;
    asm("{ .reg .u64 t; cvta.to.shared.u64 t, %1; cvt.u32.u64 %0, t; }" : "=r"(a) : "l"(p));
    return a;
}
__device__ __forceinline__ uint32_t mapa_u32(uint32_t addr, uint32_t rank) {
    uint32_t r; asm("mapa.shared::cluster.u32 %0, %1, %2;" : "=r"(r) : "r"(addr), "r"(rank));
    return r;
}
__device__ __forceinline__ void st_cluster_u64(uint32_t addr, unsigned long long v) {
    asm volatile("st.relaxed.cluster.shared::cluster.u64 [%0], %1;" :: "r"(addr), "l"(v) : "memory");
}
__device__ __forceinline__ unsigned long long ld_cta_u64(uint32_t addr) {
    unsigned long long v;
    asm volatile("ld.relaxed.cluster.shared::cta.u64 %0, [%1];" : "=l"(v) : "r"(addr) : "memory");
    return v;
}

// ---------------- fold BN into weights (+ transpose; zero histogram) ----------------
__global__ void fold_kernel(
    const float* __restrict__ w0, const float* __restrict__ b0, const float* __restrict__ g0,
    const float* __restrict__ be0, const float* __restrict__ m0, const float* __restrict__ v0,
    const float* __restrict__ w1, const float* __restrict__ b1, const float* __restrict__ g1,
    const float* __restrict__ be1, const float* __restrict__ m1, const float* __restrict__ v1,
    const float* __restrict__ w2, const float* __restrict__ b2, const float* __restrict__ g2,
    const float* __restrict__ be2, const float* __restrict__ m2, const float* __restrict__ v2)
{
    int t = threadIdx.x;
    if (t < 65) g_bcnt[t] = 0;
    if (t < 64) {
        float s = g0[t] / sqrtf(v0[t] + 1e-5f);
        g_b0[t] = (b0[t] - m0[t]) * s + be0[t];
        for (int c = 0; c < 6; c++) g_w0[t*6+c] = w0[t*6+c] * s;
    }
    if (t < 64) {
        float s = g1[t] / sqrtf(v1[t] + 1e-5f);
        g_b1[t] = (b1[t] - m1[t]) * s + be1[t];
        for (int cc = 0; cc < 64; cc++) g_w1t[cc*64 + t] = w1[t*64+cc] * s;
    }
    if (t < 128) {
        float s = g2[t] / sqrtf(v2[t] + 1e-5f);
        g_b2[t] = (b2[t] - m2[t]) * s + be2[t];
        for (int cc = 0; cc < 64; cc++) g_w2t[cc*128 + t] = w2[t*64+cc] * s;
    }
}

// ---------------- FPS: 2-CTA cluster per batch, 4 points/thread ----------------
// Exact reference arithmetic: packed add.rn/mul.rn.f32x2 (per-lane rounding ==
// scalar rn) in the reference association order ((dx2+dy2)+dz2).
// Exchange restructure vs R7: the 32 warp LEADERS send their warp keys directly
// to the peer's skeyR[par][warp] slots (32 parallel DSMEM stores issued BEFORE
// the block barrier), so the ~215cyc transit overlaps bar + local LDS. After the
// barrier, lane L reads skeyL[par][L], polls skeyR[par][L] (phase tag, all_sync
// exit), takes per-lane max, then ONE hi/lo redux pair -> global argmax of all
// 64 warp keys. Double-buffer/phase reuse safety: peer's s+2 writes are causally
// behind all our s reads (peer s+2 send requires peer s+1 poll which requires
// our s+1 sends which follow our s reads). Keys (distbits<<32 | 8191-idx):
// u64 max == (max dist, min index) == jnp.argmax.
__global__ __launch_bounds__(1024) __cluster_dims__(2, 1, 1)
void fps_kernel(const float* __restrict__ xyz, const int* __restrict__ seed,
                float* __restrict__ out)
{
    const int b = blockIdx.x >> 1;
    const uint32_t rank = blockIdx.x & 1;
    const float* xr = xyz + (size_t)b*3*NN;
    const float* yr = xr + NN;
    const float* zr = yr + NN;
    const int tid = threadIdx.x, lane = tid & 31, warp = tid >> 5;
    const int base = (int)rank * 4096 + tid * 4;   // this thread's 4 points

    extern __shared__ float fsm[];                 // full xyz copy (96KB)
    float* sx = fsm;
    float* sy = fsm + NN;
    float* sz = fsm + 2*NN;
    __shared__ unsigned long long skeyL[2][32];
    __shared__ unsigned long long skeyR[2][32];    // filled by peer via DSMEM
    __shared__ int sfps[SS];

    // smem copy of full xyz — centroid lookups hit LDS
    {
        const float4* x4 = (const float4*)xr;
        const float4* y4 = (const float4*)yr;
        const float4* z4 = (const float4*)zr;
#pragma unroll
        for (int i = 0; i < 2; i++) {
            ((float4*)sx)[tid + i*1024] = x4[tid + i*1024];
            ((float4*)sy)[tid + i*1024] = y4[tid + i*1024];
            ((float4*)sz)[tid + i*1024] = z4[tid + i*1024];
        }
    }
    // own 4 points packed
    unsigned long long pxp[2], pyp[2], pzp[2];
    float dist[4];
    {
        const float2* x2 = (const float2*)xr;
        const float2* y2 = (const float2*)yr;
        const float2* z2 = (const float2*)zr;
#pragma unroll
        for (int i = 0; i < 2; i++) {
            float2 vx = x2[base/2 + i], vy = y2[base/2 + i], vz = z2[base/2 + i];
            pxp[i] = f2pack(vx.x, vx.y);
            pyp[i] = f2pack(vy.x, vy.y);
            pzp[i] = f2pack(vz.x, vz.y);
        }
#pragma unroll
        for (int i = 0; i < 4; i++) dist[i] = 1e10f;
    }
    if (tid < 64) ((unsigned long long*)skeyR)[tid] = 0x80000000ULL;  // wrong phase
    __syncthreads();
    asm volatile("barrier.cluster.arrive.aligned;" ::: "memory");
    asm volatile("barrier.cluster.wait.aligned;"   ::: "memory");

    const uint32_t skR_base = smem_u32(&skeyR[0][0]);
    const uint32_t peer = rank ^ 1u;

    int far = 0;
    for (int s = 0; s < SS; s++) {
        if (rank == 0 && tid == 0) sfps[s] = far;
        if (s == SS - 1) break;
        const int par = s & 1;
        const unsigned ph = (unsigned)((s >> 1) & 1);

        const float cx = sx[far], cy = sy[far], cz = sz[far];
        unsigned long long ncx2 = f2pack(-cx, -cx);
        unsigned long long ncy2 = f2pack(-cy, -cy);
        unsigned long long ncz2 = f2pack(-cz, -cz);

        float bv = -1.0f; int bi = 0;
#pragma unroll
        for (int i = 0; i < 2; i++) {
            unsigned long long dx = f2add(pxp[i], ncx2);
            unsigned long long dy = f2add(pyp[i], ncy2);
            unsigned long long dz = f2add(pzp[i], ncz2);
            unsigned long long d  = f2add(f2add(f2mul(dx,dx), f2mul(dy,dy)), f2mul(dz,dz));
            float dlo, dhi; f2unpack(d, dlo, dhi);
            float n0 = fminf(dist[2*i],   dlo); dist[2*i]   = n0;
            float n1 = fminf(dist[2*i+1], dhi); dist[2*i+1] = n1;
            if (n0 > bv) { bv = n0; bi = base + 2*i; }
            if (n1 > bv) { bv = n1; bi = base + 2*i + 1; }
        }
        // warp argmax: redux -> select -> redux (u32 order on nonneg bits;
        // max of (8191-bi) == min index on ties)
        unsigned vb = __float_as_uint(bv);
        unsigned mv = __reduce_max_sync(0xffffffffu, vb);
        unsigned cand = (vb == mv) ? (unsigned)(8191 - bi) : 0u;
        unsigned ml = __reduce_max_sync(0xffffffffu, cand);
        unsigned long long key = ((unsigned long long)mv << 32) | ml;

        // leaders: local STS + immediate DSMEM send to peer (transit overlaps bar)
        if (lane == 0) {
            skeyL[par][warp] = key;
            uint32_t dst = mapa_u32(skR_base + (uint32_t)par*256u + (uint32_t)warp*8u, peer);
            st_cluster_u64(dst, key | ((unsigned long long)ph << 31));
        }
        __syncthreads();

        // merged 64-key reduce: lane L owns skeyL[L] and (polled) skeyR[L]
        unsigned long long kL = skeyL[par][lane];
        uint32_t ra = skR_base + (uint32_t)par*256u + (uint32_t)lane*8u;
        unsigned long long kR;
        for (;;) {
            kR = ld_cta_u64(ra);
            if (__all_sync(0xffffffffu, (((unsigned)(kR >> 31)) & 1u) == ph)) break;
        }
        kR &= ~(1ULL << 31);
        unsigned long long K = (kL > kR) ? kL : kR;

        unsigned hi = (unsigned)(K >> 32), lo = (unsigned)K;
        unsigned mh  = __reduce_max_sync(0xffffffffu, hi);
        unsigned loe = (hi == mh) ? lo : 0u;
        unsigned mll = __reduce_max_sync(0xffffffffu, loe);
        far = 8191 - (int)(mll & 8191u);
    }
    __syncthreads();

    if (rank == 0) {
        int id = sfps[tid];
        float x = sx[id], y = sy[id], z = sz[id];
        out[OUT_XYZ_OFF + (size_t)b*3*SS + 0*SS + tid] = x;
        out[OUT_XYZ_OFF + (size_t)b*3*SS + 1*SS + tid] = y;
        out[OUT_XYZ_OFF + (size_t)b*3*SS + 2*SS + tid] = z;
        out[OUT_SEED_OFF + (size_t)b*SS + tid] = (float)seed[(size_t)b*NN + id];
        g_cent[((size_t)b*SS + tid)*3 + 0] = x;
        g_cent[((size_t)b*SS + tid)*3 + 1] = y;
        g_cent[((size_t)b*SS + tid)*3 + 2] = z;
    }

    asm volatile("barrier.cluster.arrive.aligned;" ::: "memory");
    asm volatile("barrier.cluster.wait.aligned;"   ::: "memory");
}

// ---------------- ball query: warp per centroid, 2 points/thread -------------
// Exact per-point reference math. Dual-ballot rank preserves index order.
// Also buckets each centroid by cnt for the mlp counting sort.
__global__ __launch_bounds__(256) void ballq_kernel(const float* __restrict__ xyz)
{
    const int gw = blockIdx.x * 8 + (threadIdx.x >> 5);
    const int lane = threadIdx.x & 31;
    const int b = gw >> 10;
    const int s = gw & 1023;
    const float* xr = xyz + (size_t)b*3*NN;
    const float* yr = xr + NN;
    const float* zr = yr + NN;

    const float cx = g_cent[((size_t)b*SS+s)*3+0];
    const float cy = g_cent[((size_t)b*SS+s)*3+1];
    const float cz = g_cent[((size_t)b*SS+s)*3+2];
    const float s2 = __fadd_rn(__fadd_rn(__fmul_rn(cx,cx), __fmul_rn(cy,cy)), __fmul_rn(cz,cz));

    __shared__ int sgi[8][KK];
    int* mygi = sgi[threadIdx.x >> 5];

    int cnt = 0;
    const unsigned below = (1u << lane) - 1u;
    for (int j0 = 0; j0 < NN; j0 += 64) {
        int j = j0 + 2*lane;
        float2 xv = *(const float2*)&xr[j];
        float2 yv = *(const float2*)&yr[j];
        float2 zv = *(const float2*)&zr[j];

        float d2a  = __fadd_rn(__fadd_rn(__fmul_rn(xv.x,xv.x), __fmul_rn(yv.x,yv.x)), __fmul_rn(zv.x,zv.x));
        float dota = __fadd_rn(__fadd_rn(__fmul_rn(cx,xv.x),  __fmul_rn(cy,yv.x)),  __fmul_rn(cz,zv.x));
        float sqa  = __fadd_rn(__fadd_rn(__fmul_rn(-2.0f, dota), s2), d2a);
        float d2b  = __fadd_rn(__fadd_rn(__fmul_rn(xv.y,xv.y), __fmul_rn(yv.y,yv.y)), __fmul_rn(zv.y,zv.y));
        float dotb = __fadd_rn(__fadd_rn(__fmul_rn(cx,xv.y),  __fmul_rn(cy,yv.y)),  __fmul_rn(cz,zv.y));
        float sqb  = __fadd_rn(__fadd_rn(__fmul_rn(-2.0f, dotb), s2), d2b);

        int pa = !(sqa > 0.04f);
        int pb = !(sqb > 0.04f);
        unsigned mA = __ballot_sync(0xffffffffu, pa);
        unsigned mB = __ballot_sync(0xffffffffu, pb);
        int rA = __popc(mA & below) + __popc(mB & below);
        int rB = rA + pa;
        if (pa && (cnt + rA) < KK) mygi[cnt + rA] = j;
        if (pb && (cnt + rB) < KK) mygi[cnt + rB] = j + 1;
        cnt += __popc(mA) + __popc(mB);
        if (cnt >= KK) { cnt = KK; break; }
    }
    __syncwarp();
    if (lane == 0) {
        int gs = gw;
        g_cnt[gs] = cnt;
        g_rank[gs] = atomicAdd(&g_bcnt[cnt], 1);
    }
    for (int k = lane; k < cnt; k += 32)
        g_gi[((size_t)gw)*KK + k] = mygi[k];
}

// ---------------- counting sort: scan buckets + scatter permutation ----------
__global__ __launch_bounds__(1024) void sortc_kernel()
{
    __shared__ int soff[65];
    const int tid = threadIdx.x;
    if (tid == 0) {
        int acc = 0;
        for (int i = 0; i <= 64; i++) { int t = g_bcnt[i]; soff[i] = acc; acc += t; }
    }
    __syncthreads();
    for (int gs = tid; gs < BB*SS; gs += 1024) {
        int c = g_cnt[gs];
        g_perm[soff[c] + g_rank[gs]] = gs;
    }
}

// ---------------- fused gather + 3-layer MLP + maxpool (width-2, cnt-sorted) --
#define MW 8   // warps (centroids) per block
#define O_W1T   0
#define O_W2T   4096
#define O_B1    12288
#define O_B2    12352
#define O_GFT   12480                   // MW * 384
#define O_H1    (O_GFT + MW*384)        // MW * 128 (2 neighbors x 64)
#define O_H2    (O_H1  + MW*128)        // MW * 128
#define SMEMF   (O_H2  + MW*128)

__global__ __launch_bounds__(32*MW) void mlp_kernel(
    const float* __restrict__ xyz, const float* __restrict__ pts, float* __restrict__ out)
{
    extern __shared__ float sm[];
    float* sw1t = sm + O_W1T;
    float* sw2t = sm + O_W2T;
    float* sb1  = sm + O_B1;
    float* sb2  = sm + O_B2;

    const int tid = threadIdx.x;
    {
        const float4* s1 = (const float4*)g_w1t;
        float4* d1 = (float4*)sw1t;
        for (int i = tid; i < 1024; i += 32*MW) d1[i] = s1[i];
        const float4* s2 = (const float4*)g_w2t;
        float4* d2 = (float4*)sw2t;
        for (int i = tid; i < 2048; i += 32*MW) d2[i] = s2[i];
        for (int i = tid; i < 64;  i += 32*MW) sb1[i] = g_b1[i];
        for (int i = tid; i < 128; i += 32*MW) sb2[i] = g_b2[i];
    }
    __syncthreads();

    const int w = tid >> 5;
    const int lane = tid & 31;
    const int gs = g_perm[blockIdx.x * MW + w];   // cnt-sorted centroid id
    const int b = gs >> 10;
    const int cnt = g_cnt[gs];

    float* gft   = sm + O_GFT + w*384;
    float* h1row = sm + O_H1  + w*128;
    float* h2row = sm + O_H2  + w*128;

    const float cx = g_cent[(size_t)gs*3+0];
    const float cy = g_cent[(size_t)gs*3+1];
    const float cz = g_cent[(size_t)gs*3+2];

    // gather neighbor features up front
    {
        const int* gi = g_gi + (size_t)gs*KK;
        for (int t = lane; t < cnt*6; t += 32) {
            int k = t / 6, i = t - 6*k;
            int idx = gi[k];
            float v;
            if (i < 3) v = xyz[((size_t)b*3 + i)*NN + idx] - (i==0 ? cx : (i==1 ? cy : cz));
            else       v = pts[((size_t)b*3 + (i-3))*NN + idx];
            gft[t] = v;
        }
        if (cnt < KK && lane < 6) gft[cnt*6 + lane] = 0.0f;  // pad slot for odd cnt
    }

    const int cA = lane, cB = lane + 32;
    float w0A[6], w0B[6];
#pragma unroll
    for (int i = 0; i < 6; i++) { w0A[i] = g_w0[cA*6+i]; w0B[i] = g_w0[cB*6+i]; }
    const float b0A = g_b0[cA], b0B = g_b0[cB];
    const float b1A = sb1[cA],  b1B = sb1[cB];
    const float4 b2v = *(const float4*)&sb2[4*lane];

    float m0 = 0.f, m1 = 0.f, m2 = 0.f, m3 = 0.f;
    __syncwarp();

    for (int k = 0; k < cnt; k += 2) {
        // ---- layer 1, neighbors A=k, B=k+1 ----
        const float* fA = gft + k*6;
        const float* fB = fA + 6;
        {
            float a0 = b0A, a1 = b0B, a2 = b0A, a3 = b0B;
#pragma unroll
            for (int i = 0; i < 6; i++) {
                a0 += w0A[i]*fA[i]; a1 += w0B[i]*fA[i];
                a2 += w0A[i]*fB[i]; a3 += w0B[i]*fB[i];
            }
            h1row[cA]    = fmaxf(a0, 0.f);
            h1row[cB]    = fmaxf(a1, 0.f);
            h1row[64+cA] = fmaxf(a2, 0.f);
            h1row[64+cB] = fmaxf(a3, 0.f);
        }
        __syncwarp();

        // ---- layer 2 (weight loads shared between the 2 neighbors) ----
        float pA0 = b1A, pB0 = b1B, pA1 = b1A, pB1 = b1B;
        {
            const float4* hv = (const float4*)h1row;
#pragma unroll
            for (int c4 = 0; c4 < 16; c4++) {
                float4 ha = hv[c4];
                float4 hb = hv[16 + c4];
                const float* w1r = sw1t + c4*256;
                float a0 = w1r[cA],     a1 = w1r[64+cA], a2 = w1r[128+cA], a3 = w1r[192+cA];
                float bq0 = w1r[cB],    bq1 = w1r[64+cB], bq2 = w1r[128+cB], bq3 = w1r[192+cB];
                pA0 += a0*ha.x + a1*ha.y + a2*ha.z + a3*ha.w;
                pB0 += bq0*ha.x + bq1*ha.y + bq2*ha.z + bq3*ha.w;
                pA1 += a0*hb.x + a1*hb.y + a2*hb.z + a3*hb.w;
                pB1 += bq0*hb.x + bq1*hb.y + bq2*hb.z + bq3*hb.w;
            }
        }
        h2row[cA]    = fmaxf(pA0, 0.f);
        h2row[cB]    = fmaxf(pB0, 0.f);
        h2row[64+cA] = fmaxf(pA1, 0.f);
        h2row[64+cB] = fmaxf(pB1, 0.f);
        __syncwarp();

        // ---- layer 3 + running max (weight loads shared) ----
        float qa0=0.f,qa1=0.f,qa2=0.f,qa3=0.f;
        float qb0=0.f,qb1=0.f,qb2=0.f,qb3=0.f;
        {
            const float4* h2v = (const float4*)h2row;
#pragma unroll
            for (int c4 = 0; c4 < 16; c4++) {
                float4 ha = h2v[c4];
                float4 hb = h2v[16 + c4];
                const float* w2r = sw2t + c4*512;
                float4 wa = *(const float4*)(w2r +        4*lane);
                qa0 += wa.x*ha.x; qa1 += wa.y*ha.x; qa2 += wa.z*ha.x; qa3 += wa.w*ha.x;
                qb0 += wa.x*hb.x; qb1 += wa.y*hb.x; qb2 += wa.z*hb.x; qb3 += wa.w*hb.x;
                float4 wb = *(const float4*)(w2r + 128 + 4*lane);
                qa0 += wb.x*ha.y; qa1 += wb.y*ha.y; qa2 += wb.z*ha.y; qa3 += wb.w*ha.y;
                qb0 += wb.x*hb.y; qb1 += wb.y*hb.y; qb2 += wb.z*hb.y; qb3 += wb.w*hb.y;
                float4 wc = *(const float4*)(w2r + 256 + 4*lane);
                qa0 += wc.x*ha.z; qa1 += wc.y*ha.z; qa2 += wc.z*ha.z; qa3 += wc.w*ha.z;
                qb0 += wc.x*hb.z; qb1 += wc.y*hb.z; qb2 += wc.z*hb.z; qb3 += wc.w*hb.z;
                float4 wd = *(const float4*)(w2r + 384 + 4*lane);
                qa0 += wd.x*ha.w; qa1 += wd.y*ha.w; qa2 += wd.z*ha.w; qa3 += wd.w*ha.w;
                qb0 += wd.x*hb.w; qb1 += wd.y*hb.w; qb2 += wd.z*hb.w; qb3 += wd.w*hb.w;
            }
        }
        m0 = fmaxf(m0, fmaxf(b2v.x + qa0, 0.f));
        m1 = fmaxf(m1, fmaxf(b2v.y + qa1, 0.f));
        m2 = fmaxf(m2, fmaxf(b2v.z + qa2, 0.f));
        m3 = fmaxf(m3, fmaxf(b2v.w + qa3, 0.f));
        if (k + 1 < cnt) {  // neighbor B valid
            m0 = fmaxf(m0, fmaxf(b2v.x + qb0, 0.f));
            m1 = fmaxf(m1, fmaxf(b2v.y + qb1, 0.f));
            m2 = fmaxf(m2, fmaxf(b2v.z + qb2, 0.f));
            m3 = fmaxf(m3, fmaxf(b2v.w + qb3, 0.f));
        }
        __syncwarp();
    }

    // per-warp output (centroids are permuted -> scattered column writes)
    {
        int so = gs & 1023;
        float* dst = out + OUT_PTS_OFF + (size_t)(gs >> 10) * 128 * SS + so;
        dst[(4*lane+0)*SS] = m0;
        dst[(4*lane+1)*SS] = m1;
        dst[(4*lane+2)*SS] = m2;
        dst[(4*lane+3)*SS] = m3;
    }
}

// ---------------- launch ----------------
extern "C" void kernel_launch(void* const* d_in, const int* in_sizes, int n_in,
                              void* d_out, int out_size)
{
    const float* xyz  = (const float*)d_in[0];
    const float* pts  = (const float*)d_in[1];
    const int*   seed = (const int*)d_in[2];
    float* out = (float*)d_out;

    fold_kernel<<<1, 128>>>(
        (const float*)d_in[3],  (const float*)d_in[4],  (const float*)d_in[5],
        (const float*)d_in[6],  (const float*)d_in[7],  (const float*)d_in[8],
        (const float*)d_in[9],  (const float*)d_in[10], (const float*)d_in[11],
        (const float*)d_in[12], (const float*)d_in[13], (const float*)d_in[14],
        (const float*)d_in[15], (const float*)d_in[16], (const float*)d_in[17],
        (const float*)d_in[18], (const float*)d_in[19], (const float*)d_in[20]);

    cudaFuncSetAttribute(fps_kernel, cudaFuncAttributeMaxDynamicSharedMemorySize,
                         3*NN*sizeof(float));
    fps_kernel<<<BB*2, 1024, 3*NN*sizeof(float)>>>(xyz, seed, out);

    ballq_kernel<<<(BB*SS)/8, 256>>>(xyz);
    sortc_kernel<<<1, 1024>>>();

    cudaFuncSetAttribute(mlp_kernel, cudaFuncAttributeMaxDynamicSharedMemorySize,
                         SMEMF * sizeof(float));
    mlp_kernel<<<(BB*SS)/MW, 32*MW, SMEMF * sizeof(float)>>>(xyz, pts, out);
}

// round 12
// speedup vs baseline: 1.3238x; 1.2881x over previous
#include <cuda_runtime.h>
#include <math.h>
#include <cstdint>

#define BB 8
#define NN 8192
#define SS 1024
#define KK 64

// output layout (float32): new_xyz (B,3,S) | new_points (B,128,S) | new_seed (B,S)
#define OUT_XYZ_OFF   0
#define OUT_PTS_OFF   (BB*3*SS)                 // 24576
#define OUT_SEED_OFF  (OUT_PTS_OFF + BB*128*SS) // 1073152

// ---------------- scratch (no allocations allowed) ----------------
__device__ float g_cent[BB*SS*3];
__device__ int   g_gi[BB*SS*KK];
__device__ int   g_cnt[BB*SS];
__device__ int   g_bcnt[65];       // histogram of cnt (zeroed by fold each launch)
__device__ int   g_rank[BB*SS];    // rank within bucket
__device__ int   g_perm[BB*SS];    // centroids sorted by cnt
__device__ float g_w0[64*6],   g_b0[64];
__device__ float g_w1t[64*64], g_b1[64];    // w1t[cc*64 + c] = w1[c][cc] * s1(c)
__device__ float g_w2t[64*128], g_b2[128];  // w2t[cc*128 + o] = w2[o][cc] * s2(o)

// ---------------- f32x2 packed helpers (exact per-lane rn rounding) ----------------
__device__ __forceinline__ unsigned long long f2pack(float lo, float hi) {
    unsigned long long r;
    asm("mov.b64 %0, {%1, %2};" : "=l"(r) : "f"(lo), "f"(hi));
    return r;
}
__device__ __forceinline__ void f2unpack(unsigned long long v, float& lo, float& hi) {
    asm("mov.b64 {%0, %1}, %2;" : "=f"(lo), "=f"(hi) : "l"(v));
}
__device__ __forceinline__ unsigned long long f2add(unsigned long long a, unsigned long long b) {
    unsigned long long d;
    asm("add.rn.f32x2 %0, %1, %2;" : "=l"(d) : "l"(a), "l"(b));
    return d;
}
__device__ __forceinline__ unsigned long long f2mul(unsigned long long a, unsigned long long b) {
    unsigned long long d;
    asm("mul.rn.f32x2 %0, %1, %2;" : "=l"(d) : "l"(a), "l"(b));
    return d;
}

// ---------------- cluster helpers (DSMEM, proven R5/R7/R9) ----------------
__device__ __forceinline__ uint32_t smem_u32(const void* p) {
    uint32_t a;
    asm("{ .reg .u64 t; cvta.to.shared.u64 t, %1; cvt.u32.u64 %0, t; }" : "=r"(a) : "l"(p));
    return a;
}
__device__ __forceinline__ uint32_t mapa_u32(uint32_t addr, uint32_t rank) {
    uint32_t r; asm("mapa.shared::cluster.u32 %0, %1, %2;" : "=r"(r) : "r"(addr), "r"(rank));
    return r;
}
__device__ __forceinline__ void st_cluster_u64(uint32_t addr, unsigned long long v) {
    asm volatile("st.relaxed.cluster.shared::cluster.u64 [%0], %1;" :: "r"(addr), "l"(v) : "memory");
}
__device__ __forceinline__ unsigned long long ld_cta_u64(uint32_t addr) {
    unsigned long long v;
    asm volatile("ld.relaxed.cluster.shared::cta.u64 %0, [%1];" : "=l"(v) : "r"(addr) : "memory");
    return v;
}

// ---------------- fold BN into weights (+ transpose; zero histogram) ----------------
__global__ void fold_kernel(
    const float* __restrict__ w0, const float* __restrict__ b0, const float* __restrict__ g0,
    const float* __restrict__ be0, const float* __restrict__ m0, const float* __restrict__ v0,
    const float* __restrict__ w1, const float* __restrict__ b1, const float* __restrict__ g1,
    const float* __restrict__ be1, const float* __restrict__ m1, const float* __restrict__ v1,
    const float* __restrict__ w2, const float* __restrict__ b2, const float* __restrict__ g2,
    const float* __restrict__ be2, const float* __restrict__ m2, const float* __restrict__ v2)
{
    int t = threadIdx.x;
    if (t < 65) g_bcnt[t] = 0;
    if (t < 64) {
        float s = g0[t] / sqrtf(v0[t] + 1e-5f);
        g_b0[t] = (b0[t] - m0[t]) * s + be0[t];
        for (int c = 0; c < 6; c++) g_w0[t*6+c] = w0[t*6+c] * s;
    }
    if (t < 64) {
        float s = g1[t] / sqrtf(v1[t] + 1e-5f);
        g_b1[t] = (b1[t] - m1[t]) * s + be1[t];
        for (int cc = 0; cc < 64; cc++) g_w1t[cc*64 + t] = w1[t*64+cc] * s;
    }
    if (t < 128) {
        float s = g2[t] / sqrtf(v2[t] + 1e-5f);
        g_b2[t] = (b2[t] - m2[t]) * s + be2[t];
        for (int cc = 0; cc < 64; cc++) g_w2t[cc*128 + t] = w2[t*64+cc] * s;
    }
}

// ---------------- FPS: 8-CTA cluster per batch, 256 thr/CTA, 4 pts/thread -----
// Exact reference arithmetic: packed add.rn/mul.rn.f32x2 (per-lane rounding ==
// scalar rn) in the reference association order ((dx2+dy2)+dz2).
// Exchange: after the warp redux, each warp LEADER writes its warp key
// (phase-tagged u64) to slot [par][rank][warp] locally AND in all 7 peers
// (7 parallel DSMEM stores; transit overlaps bar + local reduce). After the
// block barrier every CTA holds the full 64-key array skeyAll[par][8][8];
// lane L polls slots L and L+32 (phase tag, all_sync exit), masks, maxes,
// then one hi/lo redux pair -> global argmax. 8 warps/CTA -> issue load ~100
// cyc/SMSP, hidden under the serial chain.
// Reuse safety (double buffer, parity s&1, phase (s>>1)&1): any writer's s+2
// store to a parity slot is causally behind our s reads of it (writer s+2
// requires writer s+1 poll, which requires OUR s+1 sends, which follow our s
// poll reads). Keys (distbits<<32 | 8191-idx): u64 max == (max dist, min
// index) == jnp.argmax at warp, block, and cluster level.
__global__ __launch_bounds__(256) __cluster_dims__(8, 1, 1)
void fps_kernel(const float* __restrict__ xyz, const int* __restrict__ seed,
                float* __restrict__ out)
{
    const int b = blockIdx.x >> 3;
    const uint32_t rank = blockIdx.x & 7;
    const float* xr = xyz + (size_t)b*3*NN;
    const float* yr = xr + NN;
    const float* zr = yr + NN;
    const int tid = threadIdx.x, lane = tid & 31, warp = tid >> 5;  // warp 0..7
    const int base = (int)rank * 1024 + tid * 4;   // this thread's 4 points

    extern __shared__ float fsm[];                 // full xyz copy (96KB)
    float* sx = fsm;
    float* sy = fsm + NN;
    float* sz = fsm + 2*NN;
    __shared__ unsigned long long skeyAll[2][8][8];  // [parity][src CTA][warp]
    __shared__ int sfps[SS];

    // smem copy of full xyz — centroid lookups hit LDS
    {
        const float4* x4 = (const float4*)xr;
        const float4* y4 = (const float4*)yr;
        const float4* z4 = (const float4*)zr;
        for (int i = tid; i < NN/4; i += 256) {
            ((float4*)sx)[i] = x4[i];
            ((float4*)sy)[i] = y4[i];
            ((float4*)sz)[i] = z4[i];
        }
    }
    // own 4 points packed
    unsigned long long pxp[2], pyp[2], pzp[2];
    float dist[4];
    {
        const float2* x2 = (const float2*)xr;
        const float2* y2 = (const float2*)yr;
        const float2* z2 = (const float2*)zr;
#pragma unroll
        for (int i = 0; i < 2; i++) {
            float2 vx = x2[base/2 + i], vy = y2[base/2 + i], vz = z2[base/2 + i];
            pxp[i] = f2pack(vx.x, vx.y);
            pyp[i] = f2pack(vy.x, vy.y);
            pzp[i] = f2pack(vz.x, vz.y);
        }
#pragma unroll
        for (int i = 0; i < 4; i++) dist[i] = 1e10f;
    }
    if (tid < 128) ((unsigned long long*)skeyAll)[tid] = 0x80000000ULL;  // wrong phase
    __syncthreads();
    asm volatile("barrier.cluster.arrive.aligned;" ::: "memory");
    asm volatile("barrier.cluster.wait.aligned;"   ::: "memory");

    const uint32_t sk_base = smem_u32(&skeyAll[0][0][0]);

    int far = 0;
    for (int s = 0; s < SS; s++) {
        if (rank == 0 && tid == 0) sfps[s] = far;
        if (s == SS - 1) break;
        const int par = s & 1;
        const unsigned ph = (unsigned)((s >> 1) & 1);

        const float cx = sx[far], cy = sy[far], cz = sz[far];
        unsigned long long ncx2 = f2pack(-cx, -cx);
        unsigned long long ncy2 = f2pack(-cy, -cy);
        unsigned long long ncz2 = f2pack(-cz, -cz);

        float bv = -1.0f; int bi = 0;
#pragma unroll
        for (int i = 0; i < 2; i++) {
            unsigned long long dx = f2add(pxp[i], ncx2);
            unsigned long long dy = f2add(pyp[i], ncy2);
            unsigned long long dz = f2add(pzp[i], ncz2);
            unsigned long long d  = f2add(f2add(f2mul(dx,dx), f2mul(dy,dy)), f2mul(dz,dz));
            float dlo, dhi; f2unpack(d, dlo, dhi);
            float n0 = fminf(dist[2*i],   dlo); dist[2*i]   = n0;
            float n1 = fminf(dist[2*i+1], dhi); dist[2*i+1] = n1;
            if (n0 > bv) { bv = n0; bi = base + 2*i; }
            if (n1 > bv) { bv = n1; bi = base + 2*i + 1; }
        }
        // warp argmax: redux -> select -> redux (u32 order on nonneg bits;
        // max of (8191-bi) == min index on ties)
        unsigned vb = __float_as_uint(bv);
        unsigned mv = __reduce_max_sync(0xffffffffu, vb);
        unsigned cand = (vb == mv) ? (unsigned)(8191 - bi) : 0u;
        unsigned ml = __reduce_max_sync(0xffffffffu, cand);
        unsigned long long tagged = (((unsigned long long)mv << 32) | ml)
                                  | ((unsigned long long)ph << 31);

        // leader: write slot [par][rank][warp] locally and in all 7 peers
        if (lane == 0) {
            uint32_t slotoff = (uint32_t)par*512u + rank*64u + (uint32_t)warp*8u;
            skeyAll[par][rank][warp] = tagged;        // local STS
            uint32_t slot = sk_base + slotoff;
#pragma unroll
            for (uint32_t p = 0; p < 8; p++) {
                if (p != rank) st_cluster_u64(mapa_u32(slot, p), tagged);
            }
        }
        __syncthreads();

        // merged 64-key reduce: lane L owns global slots L and L+32
        uint32_t a0 = sk_base + (uint32_t)par*512u + (uint32_t)lane*8u;
        uint32_t a1 = a0 + 256u;
        unsigned long long k0, k1;
        for (;;) {
            k0 = ld_cta_u64(a0);
            k1 = ld_cta_u64(a1);
            bool ok = ((((unsigned)(k0 >> 31)) & 1u) == ph) &&
                      ((((unsigned)(k1 >> 31)) & 1u) == ph);
            if (__all_sync(0xffffffffu, ok)) break;
        }
        k0 &= ~(1ULL << 31);
        k1 &= ~(1ULL << 31);
        unsigned long long K = (k0 > k1) ? k0 : k1;

        unsigned hi = (unsigned)(K >> 32), lo = (unsigned)K;
        unsigned mh  = __reduce_max_sync(0xffffffffu, hi);
        unsigned loe = (hi == mh) ? lo : 0u;
        unsigned mll = __reduce_max_sync(0xffffffffu, loe);
        far = 8191 - (int)(mll & 8191u);
    }
    __syncthreads();

    if (rank == 0) {
        for (int t = tid; t < SS; t += 256) {
            int id = sfps[t];
            float x = sx[id], y = sy[id], z = sz[id];
            out[OUT_XYZ_OFF + (size_t)b*3*SS + 0*SS + t] = x;
            out[OUT_XYZ_OFF + (size_t)b*3*SS + 1*SS + t] = y;
            out[OUT_XYZ_OFF + (size_t)b*3*SS + 2*SS + t] = z;
            out[OUT_SEED_OFF + (size_t)b*SS + t] = (float)seed[(size_t)b*NN + id];
            g_cent[((size_t)b*SS + t)*3 + 0] = x;
            g_cent[((size_t)b*SS + t)*3 + 1] = y;
            g_cent[((size_t)b*SS + t)*3 + 2] = z;
        }
    }

    asm volatile("barrier.cluster.arrive.aligned;" ::: "memory");
    asm volatile("barrier.cluster.wait.aligned;"   ::: "memory");
}

// ---------------- ball query: warp per centroid, 2 points/thread -------------
// Exact per-point reference math. Dual-ballot rank preserves index order.
// Also buckets each centroid by cnt for the mlp counting sort.
__global__ __launch_bounds__(256) void ballq_kernel(const float* __restrict__ xyz)
{
    const int gw = blockIdx.x * 8 + (threadIdx.x >> 5);
    const int lane = threadIdx.x & 31;
    const int b = gw >> 10;
    const int s = gw & 1023;
    const float* xr = xyz + (size_t)b*3*NN;
    const float* yr = xr + NN;
    const float* zr = yr + NN;

    const float cx = g_cent[((size_t)b*SS+s)*3+0];
    const float cy = g_cent[((size_t)b*SS+s)*3+1];
    const float cz = g_cent[((size_t)b*SS+s)*3+2];
    const float s2 = __fadd_rn(__fadd_rn(__fmul_rn(cx,cx), __fmul_rn(cy,cy)), __fmul_rn(cz,cz));

    __shared__ int sgi[8][KK];
    int* mygi = sgi[threadIdx.x >> 5];

    int cnt = 0;
    const unsigned below = (1u << lane) - 1u;
    for (int j0 = 0; j0 < NN; j0 += 64) {
        int j = j0 + 2*lane;
        float2 xv = *(const float2*)&xr[j];
        float2 yv = *(const float2*)&yr[j];
        float2 zv = *(const float2*)&zr[j];

        float d2a  = __fadd_rn(__fadd_rn(__fmul_rn(xv.x,xv.x), __fmul_rn(yv.x,yv.x)), __fmul_rn(zv.x,zv.x));
        float dota = __fadd_rn(__fadd_rn(__fmul_rn(cx,xv.x),  __fmul_rn(cy,yv.x)),  __fmul_rn(cz,zv.x));
        float sqa  = __fadd_rn(__fadd_rn(__fmul_rn(-2.0f, dota), s2), d2a);
        float d2b  = __fadd_rn(__fadd_rn(__fmul_rn(xv.y,xv.y), __fmul_rn(yv.y,yv.y)), __fmul_rn(zv.y,zv.y));
        float dotb = __fadd_rn(__fadd_rn(__fmul_rn(cx,xv.y),  __fmul_rn(cy,yv.y)),  __fmul_rn(cz,zv.y));
        float sqb  = __fadd_rn(__fadd_rn(__fmul_rn(-2.0f, dotb), s2), d2b);

        int pa = !(sqa > 0.04f);
        int pb = !(sqb > 0.04f);
        unsigned mA = __ballot_sync(0xffffffffu, pa);
        unsigned mB = __ballot_sync(0xffffffffu, pb);
        int rA = __popc(mA & below) + __popc(mB & below);
        int rB = rA + pa;
        if (pa && (cnt + rA) < KK) mygi[cnt + rA] = j;
        if (pb && (cnt + rB) < KK) mygi[cnt + rB] = j + 1;
        cnt += __popc(mA) + __popc(mB);
        if (cnt >= KK) { cnt = KK; break; }
    }
    __syncwarp();
    if (lane == 0) {
        g_cnt[gw] = cnt;
        g_rank[gw] = atomicAdd(&g_bcnt[cnt], 1);
    }
    for (int k = lane; k < cnt; k += 32)
        g_gi[((size_t)gw)*KK + k] = mygi[k];
}

// ---------------- counting sort: scan buckets + scatter permutation ----------
__global__ __launch_bounds__(1024) void sortc_kernel()
{
    __shared__ int soff[65];
    const int tid = threadIdx.x;
    if (tid == 0) {
        int acc = 0;
        for (int i = 0; i <= 64; i++) { int t = g_bcnt[i]; soff[i] = acc; acc += t; }
    }
    __syncthreads();
    for (int gs = tid; gs < BB*SS; gs += 1024) {
        int c = g_cnt[gs];
        g_perm[soff[c] + g_rank[gs]] = gs;
    }
}

// ---------------- fused gather + 3-layer MLP + maxpool (width-2, cnt-sorted) --
#define MW 8   // warps (centroids) per block
#define O_W1T   0
#define O_W2T   4096
#define O_B1    12288
#define O_B2    12352
#define O_GFT   12480                   // MW * 384
#define O_H1    (O_GFT + MW*384)        // MW * 128 (2 neighbors x 64)
#define O_H2    (O_H1  + MW*128)        // MW * 128
#define SMEMF   (O_H2  + MW*128)

__global__ __launch_bounds__(32*MW) void mlp_kernel(
    const float* __restrict__ xyz, const float* __restrict__ pts, float* __restrict__ out)
{
    extern __shared__ float sm[];
    float* sw1t = sm + O_W1T;
    float* sw2t = sm + O_W2T;
    float* sb1  = sm + O_B1;
    float* sb2  = sm + O_B2;

    const int tid = threadIdx.x;
    {
        const float4* s1 = (const float4*)g_w1t;
        float4* d1 = (float4*)sw1t;
        for (int i = tid; i < 1024; i += 32*MW) d1[i] = s1[i];
        const float4* s2 = (const float4*)g_w2t;
        float4* d2 = (float4*)sw2t;
        for (int i = tid; i < 2048; i += 32*MW) d2[i] = s2[i];
        for (int i = tid; i < 64;  i += 32*MW) sb1[i] = g_b1[i];
        for (int i = tid; i < 128; i += 32*MW) sb2[i] = g_b2[i];
    }
    __syncthreads();

    const int w = tid >> 5;
    const int lane = tid & 31;
    const int gs = g_perm[blockIdx.x * MW + w];   // cnt-sorted centroid id
    const int b = gs >> 10;
    const int cnt = g_cnt[gs];

    float* gft   = sm + O_GFT + w*384;
    float* h1row = sm + O_H1  + w*128;
    float* h2row = sm + O_H2  + w*128;

    const float cx = g_cent[(size_t)gs*3+0];
    const float cy = g_cent[(size_t)gs*3+1];
    const float cz = g_cent[(size_t)gs*3+2];

    // gather neighbor features up front
    {
        const int* gi = g_gi + (size_t)gs*KK;
        for (int t = lane; t < cnt*6; t += 32) {
            int k = t / 6, i = t - 6*k;
            int idx = gi[k];
            float v;
            if (i < 3) v = xyz[((size_t)b*3 + i)*NN + idx] - (i==0 ? cx : (i==1 ? cy : cz));
            else       v = pts[((size_t)b*3 + (i-3))*NN + idx];
            gft[t] = v;
        }
        if (cnt < KK && lane < 6) gft[cnt*6 + lane] = 0.0f;  // pad slot for odd cnt
    }

    const int cA = lane, cB = lane + 32;
    float w0A[6], w0B[6];
#pragma unroll
    for (int i = 0; i < 6; i++) { w0A[i] = g_w0[cA*6+i]; w0B[i] = g_w0[cB*6+i]; }
    const float b0A = g_b0[cA], b0B = g_b0[cB];
    const float b1A = sb1[cA],  b1B = sb1[cB];
    const float4 b2v = *(const float4*)&sb2[4*lane];

    float m0 = 0.f, m1 = 0.f, m2 = 0.f, m3 = 0.f;
    __syncwarp();

    for (int k = 0; k < cnt; k += 2) {
        // ---- layer 1, neighbors A=k, B=k+1 ----
        const float* fA = gft + k*6;
        const float* fB = fA + 6;
        {
            float a0 = b0A, a1 = b0B, a2 = b0A, a3 = b0B;
#pragma unroll
            for (int i = 0; i < 6; i++) {
                a0 += w0A[i]*fA[i]; a1 += w0B[i]*fA[i];
                a2 += w0A[i]*fB[i]; a3 += w0B[i]*fB[i];
            }
            h1row[cA]    = fmaxf(a0, 0.f);
            h1row[cB]    = fmaxf(a1, 0.f);
            h1row[64+cA] = fmaxf(a2, 0.f);
            h1row[64+cB] = fmaxf(a3, 0.f);
        }
        __syncwarp();

        // ---- layer 2 (weight loads shared between the 2 neighbors) ----
        float pA0 = b1A, pB0 = b1B, pA1 = b1A, pB1 = b1B;
        {
            const float4* hv = (const float4*)h1row;
#pragma unroll
            for (int c4 = 0; c4 < 16; c4++) {
                float4 ha = hv[c4];
                float4 hb = hv[16 + c4];
                const float* w1r = sw1t + c4*256;
                float a0 = w1r[cA],     a1 = w1r[64+cA], a2 = w1r[128+cA], a3 = w1r[192+cA];
                float bq0 = w1r[cB],    bq1 = w1r[64+cB], bq2 = w1r[128+cB], bq3 = w1r[192+cB];
                pA0 += a0*ha.x + a1*ha.y + a2*ha.z + a3*ha.w;
                pB0 += bq0*ha.x + bq1*ha.y + bq2*ha.z + bq3*ha.w;
                pA1 += a0*hb.x + a1*hb.y + a2*hb.z + a3*hb.w;
                pB1 += bq0*hb.x + bq1*hb.y + bq2*hb.z + bq3*hb.w;
            }
        }
        h2row[cA]    = fmaxf(pA0, 0.f);
        h2row[cB]    = fmaxf(pB0, 0.f);
        h2row[64+cA] = fmaxf(pA1, 0.f);
        h2row[64+cB] = fmaxf(pB1, 0.f);
        __syncwarp();

        // ---- layer 3 + running max (weight loads shared) ----
        float qa0=0.f,qa1=0.f,qa2=0.f,qa3=0.f;
        float qb0=0.f,qb1=0.f,qb2=0.f,qb3=0.f;
        {
            const float4* h2v = (const float4*)h2row;
#pragma unroll
            for (int c4 = 0; c4 < 16; c4++) {
                float4 ha = h2v[c4];
                float4 hb = h2v[16 + c4];
                const float* w2r = sw2t + c4*512;
                float4 wa = *(const float4*)(w2r +        4*lane);
                qa0 += wa.x*ha.x; qa1 += wa.y*ha.x; qa2 += wa.z*ha.x; qa3 += wa.w*ha.x;
                qb0 += wa.x*hb.x; qb1 += wa.y*hb.x; qb2 += wa.z*hb.x; qb3 += wa.w*hb.x;
                float4 wb = *(const float4*)(w2r + 128 + 4*lane);
                qa0 += wb.x*ha.y; qa1 += wb.y*ha.y; qa2 += wb.z*ha.y; qa3 += wb.w*ha.y;
                qb0 += wb.x*hb.y; qb1 += wb.y*hb.y; qb2 += wb.z*hb.y; qb3 += wb.w*hb.y;
                float4 wc = *(const float4*)(w2r + 256 + 4*lane);
                qa0 += wc.x*ha.z; qa1 += wc.y*ha.z; qa2 += wc.z*ha.z; qa3 += wc.w*ha.z;
                qb0 += wc.x*hb.z; qb1 += wc.y*hb.z; qb2 += wc.z*hb.z; qb3 += wc.w*hb.z;
                float4 wd = *(const float4*)(w2r + 384 + 4*lane);
                qa0 += wd.x*ha.w; qa1 += wd.y*ha.w; qa2 += wd.z*ha.w; qa3 += wd.w*ha.w;
                qb0 += wd.x*hb.w; qb1 += wd.y*hb.w; qb2 += wd.z*hb.w; qb3 += wd.w*hb.w;
            }
        }
        m0 = fmaxf(m0, fmaxf(b2v.x + qa0, 0.f));
        m1 = fmaxf(m1, fmaxf(b2v.y + qa1, 0.f));
        m2 = fmaxf(m2, fmaxf(b2v.z + qa2, 0.f));
        m3 = fmaxf(m3, fmaxf(b2v.w + qa3, 0.f));
        if (k + 1 < cnt) {  // neighbor B valid
            m0 = fmaxf(m0, fmaxf(b2v.x + qb0, 0.f));
            m1 = fmaxf(m1, fmaxf(b2v.y + qb1, 0.f));
            m2 = fmaxf(m2, fmaxf(b2v.z + qb2, 0.f));
            m3 = fmaxf(m3, fmaxf(b2v.w + qb3, 0.f));
        }
        __syncwarp();
    }

    // per-warp output (centroids are permuted -> scattered column writes)
    {
        int so = gs & 1023;
        float* dst = out + OUT_PTS_OFF + (size_t)(gs >> 10) * 128 * SS + so;
        dst[(4*lane+0)*SS] = m0;
        dst[(4*lane+1)*SS] = m1;
        dst[(4*lane+2)*SS] = m2;
        dst[(4*lane+3)*SS] = m3;
    }
}

// ---------------- launch ----------------
extern "C" void kernel_launch(void* const* d_in, const int* in_sizes, int n_in,
                              void* d_out, int out_size)
{
    const float* xyz  = (const float*)d_in[0];
    const float* pts  = (const float*)d_in[1];
    const int*   seed = (const int*)d_in[2];
    float* out = (float*)d_out;

    fold_kernel<<<1, 128>>>(
        (const float*)d_in[3],  (const float*)d_in[4],  (const float*)d_in[5],
        (const float*)d_in[6],  (const float*)d_in[7],  (const float*)d_in[8],
        (const float*)d_in[9],  (const float*)d_in[10], (const float*)d_in[11],
        (const float*)d_in[12], (const float*)d_in[13], (const float*)d_in[14],
        (const float*)d_in[15], (const float*)d_in[16], (const float*)d_in[17],
        (const float*)d_in[18], (const float*)d_in[19], (const float*)d_in[20]);

    cudaFuncSetAttribute(fps_kernel, cudaFuncAttributeMaxDynamicSharedMemorySize,
                         3*NN*sizeof(float));
    fps_kernel<<<BB*8, 256, 3*NN*sizeof(float)>>>(xyz, seed, out);

    ballq_kernel<<<(BB*SS)/8, 256>>>(xyz);
    sortc_kernel<<<1, 1024>>>();

    cudaFuncSetAttribute(mlp_kernel, cudaFuncAttributeMaxDynamicSharedMemorySize,
                         SMEMF * sizeof(float));
    mlp_kernel<<<(BB*SS)/MW, 32*MW, SMEMF * sizeof(float)>>>(xyz, pts, out);
}

// round 16
// speedup vs baseline: 1.3501x; 1.0199x over previous
#include <cuda_runtime.h>
#include <math.h>
#include <cstdint>

#define BB 8
#define NN 8192
#define SS 1024
#define KK 64

// output layout (float32): new_xyz (B,3,S) | new_points (B,128,S) | new_seed (B,S)
#define OUT_XYZ_OFF   0
#define OUT_PTS_OFF   (BB*3*SS)                 // 24576
#define OUT_SEED_OFF  (OUT_PTS_OFF + BB*128*SS) // 1073152

// ---------------- scratch (no allocations allowed) ----------------
__device__ float g_cent[BB*SS*3];
__device__ int   g_gi[BB*SS*KK];
__device__ int   g_cnt[BB*SS];
__device__ int   g_bcnt[65];       // histogram of cnt (zeroed by fold each launch)
__device__ int   g_rank[BB*SS];    // rank within bucket
__device__ int   g_perm[BB*SS];    // centroids sorted by cnt
__device__ float g_w0[64*6],   g_b0[64];
__device__ float g_w1t[64*64], g_b1[64];    // w1t[cc*64 + c] = w1[c][cc] * s1(c)
__device__ float g_w2t[64*128], g_b2[128];  // w2t[cc*128 + o] = w2[o][cc] * s2(o)

// ---------------- f32x2 packed helpers (exact per-lane rn rounding) ----------------
__device__ __forceinline__ unsigned long long f2pack(float lo, float hi) {
    unsigned long long r;
    asm("mov.b64 %0, {%1, %2};" : "=l"(r) : "f"(lo), "f"(hi));
    return r;
}
__device__ __forceinline__ void f2unpack(unsigned long long v, float& lo, float& hi) {
    asm("mov.b64 {%0, %1}, %2;" : "=f"(lo), "=f"(hi) : "l"(v));
}
__device__ __forceinline__ unsigned long long f2add(unsigned long long a, unsigned long long b) {
    unsigned long long d;
    asm("add.rn.f32x2 %0, %1, %2;" : "=l"(d) : "l"(a), "l"(b));
    return d;
}
__device__ __forceinline__ unsigned long long f2mul(unsigned long long a, unsigned long long b) {
    unsigned long long d;
    asm("mul.rn.f32x2 %0, %1, %2;" : "=l"(d) : "l"(a), "l"(b));
    return d;
}

// ---------------- cluster helpers (DSMEM, proven R5/R7/R9/R12) ----------------
__device__ __forceinline__ uint32_t smem_u32(const void* p) {
    uint32_t a;
    asm("{ .reg .u64 t; cvta.to.shared.u64 t, %1; cvt.u32.u64 %0, t; }" : "=r"(a) : "l"(p));
    return a;
}
__device__ __forceinline__ uint32_t mapa_u32(uint32_t addr, uint32_t rank) {
    uint32_t r; asm("mapa.shared::cluster.u32 %0, %1, %2;" : "=r"(r) : "r"(addr), "r"(rank));
    return r;
}
__device__ __forceinline__ void st_cluster_u64(uint32_t addr, unsigned long long v) {
    asm volatile("st.relaxed.cluster.shared::cluster.u64 [%0], %1;" :: "r"(addr), "l"(v) : "memory");
}
__device__ __forceinline__ unsigned long long ld_cta_u64(uint32_t addr) {
    unsigned long long v;
    asm volatile("ld.relaxed.cluster.shared::cta.u64 %0, [%1];" : "=l"(v) : "r"(addr) : "memory");
    return v;
}

// ---------------- fold BN into weights (+ transpose; zero histogram) ----------------
__global__ void fold_kernel(
    const float* __restrict__ w0, const float* __restrict__ b0, const float* __restrict__ g0,
    const float* __restrict__ be0, const float* __restrict__ m0, const float* __restrict__ v0,
    const float* __restrict__ w1, const float* __restrict__ b1, const float* __restrict__ g1,
    const float* __restrict__ be1, const float* __restrict__ m1, const float* __restrict__ v1,
    const float* __restrict__ w2, const float* __restrict__ b2, const float* __restrict__ g2,
    const float* __restrict__ be2, const float* __restrict__ m2, const float* __restrict__ v2)
{
    int t = threadIdx.x;
    if (t < 65) g_bcnt[t] = 0;
    if (t < 64) {
        float s = g0[t] / sqrtf(v0[t] + 1e-5f);
        g_b0[t] = (b0[t] - m0[t]) * s + be0[t];
        for (int c = 0; c < 6; c++) g_w0[t*6+c] = w0[t*6+c] * s;
    }
    if (t < 64) {
        float s = g1[t] / sqrtf(v1[t] + 1e-5f);
        g_b1[t] = (b1[t] - m1[t]) * s + be1[t];
        for (int cc = 0; cc < 64; cc++) g_w1t[cc*64 + t] = w1[t*64+cc] * s;
    }
    if (t < 128) {
        float s = g2[t] / sqrtf(v2[t] + 1e-5f);
        g_b2[t] = (b2[t] - m2[t]) * s + be2[t];
        for (int cc = 0; cc < 64; cc++) g_w2t[cc*128 + t] = w2[t*64+cc] * s;
    }
}

// ---------------- FPS: 8-CTA cluster per batch, 256 thr/CTA, 4 pts/thread -----
// Exact reference arithmetic: packed add.rn/mul.rn.f32x2 (per-lane rounding ==
// scalar rn) in the reference association order ((dx2+dy2)+dz2).
// NO __syncthreads inside the loop. Correctness without it:
//  - Visibility: every slot's 64-bit key carries its phase tag; each warp's
//    poll spins until ALL 64 slots (local ones included) show phase(s).
//  - Reuse/termination: any writer's s+2 store to a slot is causally behind
//    every reader's s poll of that slot (writer s+2 <- writer s+1 poll <-
//    reader's s+1 send <- reader's s poll pass). Max warp drift ~1 iteration
//    << 2-deep parity buffer; phases of s and s+2 differ.
// Keys (distbits<<32 | 8191-idx): u64 max == (max dist, min index) ==
// jnp.argmax at warp, block, and cluster level.
__global__ __launch_bounds__(256) __cluster_dims__(8, 1, 1)
void fps_kernel(const float* __restrict__ xyz, const int* __restrict__ seed,
                float* __restrict__ out)
{
    const int b = blockIdx.x >> 3;
    const uint32_t rank = blockIdx.x & 7;
    const float* xr = xyz + (size_t)b*3*NN;
    const float* yr = xr + NN;
    const float* zr = yr + NN;
    const int tid = threadIdx.x, lane = tid & 31, warp = tid >> 5;  // warp 0..7
    const int base = (int)rank * 1024 + tid * 4;   // this thread's 4 points

    extern __shared__ float fsm[];                 // full xyz copy (96KB)
    float* sx = fsm;
    float* sy = fsm + NN;
    float* sz = fsm + 2*NN;
    __shared__ unsigned long long skeyAll[2][8][8];  // [parity][src CTA][warp]
    __shared__ int sfps[SS];

    // smem copy of full xyz — centroid lookups hit LDS
    {
        const float4* x4 = (const float4*)xr;
        const float4* y4 = (const float4*)yr;
        const float4* z4 = (const float4*)zr;
        for (int i = tid; i < NN/4; i += 256) {
            ((float4*)sx)[i] = x4[i];
            ((float4*)sy)[i] = y4[i];
            ((float4*)sz)[i] = z4[i];
        }
    }
    // own 4 points packed
    unsigned long long pxp[2], pyp[2], pzp[2];
    float dist[4];
    {
        const float2* x2 = (const float2*)xr;
        const float2* y2 = (const float2*)yr;
        const float2* z2 = (const float2*)zr;
#pragma unroll
        for (int i = 0; i < 2; i++) {
            float2 vx = x2[base/2 + i], vy = y2[base/2 + i], vz = z2[base/2 + i];
            pxp[i] = f2pack(vx.x, vx.y);
            pyp[i] = f2pack(vy.x, vy.y);
            pzp[i] = f2pack(vz.x, vz.y);
        }
#pragma unroll
        for (int i = 0; i < 4; i++) dist[i] = 1e10f;
    }
    if (tid < 128) ((unsigned long long*)skeyAll)[tid] = 0x80000000ULL;  // wrong phase
    __syncthreads();
    asm volatile("barrier.cluster.arrive.aligned;" ::: "memory");
    asm volatile("barrier.cluster.wait.aligned;"   ::: "memory");

    const uint32_t sk_base = smem_u32(&skeyAll[0][0][0]);

    int far = 0;
    for (int s = 0; s < SS; s++) {
        if (rank == 0 && tid == 0) sfps[s] = far;
        if (s == SS - 1) break;
        const int par = s & 1;
        const unsigned ph = (unsigned)((s >> 1) & 1);

        const float cx = sx[far], cy = sy[far], cz = sz[far];
        unsigned long long ncx2 = f2pack(-cx, -cx);
        unsigned long long ncy2 = f2pack(-cy, -cy);
        unsigned long long ncz2 = f2pack(-cz, -cz);

        float bv = -1.0f; int bi = 0;
#pragma unroll
        for (int i = 0; i < 2; i++) {
            unsigned long long dx = f2add(pxp[i], ncx2);
            unsigned long long dy = f2add(pyp[i], ncy2);
            unsigned long long dz = f2add(pzp[i], ncz2);
            unsigned long long d  = f2add(f2add(f2mul(dx,dx), f2mul(dy,dy)), f2mul(dz,dz));
            float dlo, dhi; f2unpack(d, dlo, dhi);
            float n0 = fminf(dist[2*i],   dlo); dist[2*i]   = n0;
            float n1 = fminf(dist[2*i+1], dhi); dist[2*i+1] = n1;
            if (n0 > bv) { bv = n0; bi = base + 2*i; }
            if (n1 > bv) { bv = n1; bi = base + 2*i + 1; }
        }
        // warp argmax: redux -> select -> redux (u32 order on nonneg bits;
        // max of (8191-bi) == min index on ties)
        unsigned vb = __float_as_uint(bv);
        unsigned mv = __reduce_max_sync(0xffffffffu, vb);
        unsigned cand = (vb == mv) ? (unsigned)(8191 - bi) : 0u;
        unsigned ml = __reduce_max_sync(0xffffffffu, cand);
        unsigned long long tagged = (((unsigned long long)mv << 32) | ml)
                                  | ((unsigned long long)ph << 31);

        // leader: write slot [par][rank][warp] locally and in all 7 peers
        if (lane == 0) {
            uint32_t slotoff = (uint32_t)par*512u + rank*64u + (uint32_t)warp*8u;
            skeyAll[par][rank][warp] = tagged;        // local STS (phase-tagged)
            uint32_t slot = sk_base + slotoff;
#pragma unroll
            for (uint32_t p = 0; p < 8; p++) {
                if (p != rank) st_cluster_u64(mapa_u32(slot, p), tagged);
            }
        }
        // NO __syncthreads here (see header comment for the proof)

        // merged 64-key reduce: lane L owns global slots L and L+32
        uint32_t a0 = sk_base + (uint32_t)par*512u + (uint32_t)lane*8u;
        uint32_t a1 = a0 + 256u;
        unsigned long long k0, k1;
        for (;;) {
            k0 = ld_cta_u64(a0);
            k1 = ld_cta_u64(a1);
            bool ok = ((((unsigned)(k0 >> 31)) & 1u) == ph) &&
                      ((((unsigned)(k1 >> 31)) & 1u) == ph);
            if (__all_sync(0xffffffffu, ok)) break;
        }
        k0 &= ~(1ULL << 31);
        k1 &= ~(1ULL << 31);
        unsigned long long K = (k0 > k1) ? k0 : k1;

        unsigned hi = (unsigned)(K >> 32), lo = (unsigned)K;
        unsigned mh  = __reduce_max_sync(0xffffffffu, hi);
        unsigned loe = (hi == mh) ? lo : 0u;
        unsigned mll = __reduce_max_sync(0xffffffffu, loe);
        far = 8191 - (int)(mll & 8191u);
    }
    __syncthreads();

    if (rank == 0) {
        for (int t = tid; t < SS; t += 256) {
            int id = sfps[t];
            float x = sx[id], y = sy[id], z = sz[id];
            out[OUT_XYZ_OFF + (size_t)b*3*SS + 0*SS + t] = x;
            out[OUT_XYZ_OFF + (size_t)b*3*SS + 1*SS + t] = y;
            out[OUT_XYZ_OFF + (size_t)b*3*SS + 2*SS + t] = z;
            out[OUT_SEED_OFF + (size_t)b*SS + t] = (float)seed[(size_t)b*NN + id];
            g_cent[((size_t)b*SS + t)*3 + 0] = x;
            g_cent[((size_t)b*SS + t)*3 + 1] = y;
            g_cent[((size_t)b*SS + t)*3 + 2] = z;
        }
    }

    asm volatile("barrier.cluster.arrive.aligned;" ::: "memory");
    asm volatile("barrier.cluster.wait.aligned;"   ::: "memory");
}

// ---------------- ball query: warp per centroid, 4 points/thread -------------
// Exact per-point reference math. Quad-ballot rank preserves index order:
// lane L holds points j0+4L+i; rank(point) = (in-radius points of lower lanes
// across all 4 sub-ballots) + (own lane's earlier subs).
__global__ __launch_bounds__(256) void ballq_kernel(const float* __restrict__ xyz)
{
    const int gw = blockIdx.x * 8 + (threadIdx.x >> 5);
    const int lane = threadIdx.x & 31;
    const int b = gw >> 10;
    const int s = gw & 1023;
    const float* xr = xyz + (size_t)b*3*NN;
    const float* yr = xr + NN;
    const float* zr = yr + NN;

    const float cx = g_cent[((size_t)b*SS+s)*3+0];
    const float cy = g_cent[((size_t)b*SS+s)*3+1];
    const float cz = g_cent[((size_t)b*SS+s)*3+2];
    const float s2 = __fadd_rn(__fadd_rn(__fmul_rn(cx,cx), __fmul_rn(cy,cy)), __fmul_rn(cz,cz));

    __shared__ int sgi[8][KK];
    int* mygi = sgi[threadIdx.x >> 5];

    int cnt = 0;
    const unsigned below = (1u << lane) - 1u;
    for (int j0 = 0; j0 < NN; j0 += 128) {
        int j = j0 + 4*lane;
        float4 xv = *(const float4*)&xr[j];
        float4 yv = *(const float4*)&yr[j];
        float4 zv = *(const float4*)&zr[j];

        float sq[4];
        {
            float xs[4] = {xv.x, xv.y, xv.z, xv.w};
            float ys[4] = {yv.x, yv.y, yv.z, yv.w};
            float zs[4] = {zv.x, zv.y, zv.z, zv.w};
#pragma unroll
            for (int i = 0; i < 4; i++) {
                float d2  = __fadd_rn(__fadd_rn(__fmul_rn(xs[i],xs[i]), __fmul_rn(ys[i],ys[i])), __fmul_rn(zs[i],zs[i]));
                float dot = __fadd_rn(__fadd_rn(__fmul_rn(cx,xs[i]),  __fmul_rn(cy,ys[i])),  __fmul_rn(cz,zs[i]));
                sq[i]     = __fadd_rn(__fadd_rn(__fmul_rn(-2.0f, dot), s2), d2);
            }
        }
        int pa = !(sq[0] > 0.04f);
        int pb = !(sq[1] > 0.04f);
        int pc = !(sq[2] > 0.04f);
        int pd = !(sq[3] > 0.04f);
        unsigned mA = __ballot_sync(0xffffffffu, pa);
        unsigned mB = __ballot_sync(0xffffffffu, pb);
        unsigned mC = __ballot_sync(0xffffffffu, pc);
        unsigned mD = __ballot_sync(0xffffffffu, pd);
        int rA = __popc(mA & below) + __popc(mB & below) + __popc(mC & below) + __popc(mD & below);
        int rB = rA + pa;
        int rC = rB + pb;
        int rD = rC + pc;
        if (pa && (cnt + rA) < KK) mygi[cnt + rA] = j;
        if (pb && (cnt + rB) < KK) mygi[cnt + rB] = j + 1;
        if (pc && (cnt + rC) < KK) mygi[cnt + rC] = j + 2;
        if (pd && (cnt + rD) < KK) mygi[cnt + rD] = j + 3;
        cnt += __popc(mA) + __popc(mB) + __popc(mC) + __popc(mD);
        if (cnt >= KK) { cnt = KK; break; }
    }
    __syncwarp();
    if (lane == 0) {
        g_cnt[gw] = cnt;
        g_rank[gw] = atomicAdd(&g_bcnt[cnt], 1);
    }
    for (int k = lane; k < cnt; k += 32)
        g_gi[((size_t)gw)*KK + k] = mygi[k];
}

// ---------------- counting sort: parallel scan + scatter permutation ----------
__global__ __launch_bounds__(1024) void sortc_kernel()
{
    __shared__ int sv[65];
    __shared__ int soff[65];
    const int tid = threadIdx.x;
    int myc = 0;
    if (tid < 65) { myc = g_bcnt[tid]; sv[tid] = myc; }
    __syncthreads();
    // Hillis-Steele inclusive scan over 65 entries
    for (int off = 1; off < 65; off <<= 1) {
        int v = 0;
        if (tid < 65 && tid >= off) v = sv[tid - off];
        __syncthreads();
        if (tid < 65) sv[tid] += v;
        __syncthreads();
    }
    if (tid < 65) soff[tid] = sv[tid] - myc;   // exclusive
    __syncthreads();
    for (int gs = tid; gs < BB*SS; gs += 1024) {
        int c = g_cnt[gs];
        g_perm[soff[c] + g_rank[gs]] = gs;
    }
}

// ---------------- fused gather + 3-layer MLP + maxpool (width-2, cnt-sorted) --
#define MW 8   // warps (centroids) per block
#define O_W1T   0
#define O_W2T   4096
#define O_B1    12288
#define O_B2    12352
#define O_GFT   12480                   // MW * 384
#define O_H1    (O_GFT + MW*384)        // MW * 128 (2 neighbors x 64)
#define O_H2    (O_H1  + MW*128)        // MW * 128
#define SMEMF   (O_H2  + MW*128)

__global__ __launch_bounds__(32*MW) void mlp_kernel(
    const float* __restrict__ xyz, const float* __restrict__ pts, float* __restrict__ out)
{
    extern __shared__ float sm[];
    float* sw1t = sm + O_W1T;
    float* sw2t = sm + O_W2T;
    float* sb1  = sm + O_B1;
    float* sb2  = sm + O_B2;

    const int tid = threadIdx.x;
    {
        const float4* s1 = (const float4*)g_w1t;
        float4* d1 = (float4*)sw1t;
        for (int i = tid; i < 1024; i += 32*MW) d1[i] = s1[i];
        const float4* s2 = (const float4*)g_w2t;
        float4* d2 = (float4*)sw2t;
        for (int i = tid; i < 2048; i += 32*MW) d2[i] = s2[i];
        for (int i = tid; i < 64;  i += 32*MW) sb1[i] = g_b1[i];
        for (int i = tid; i < 128; i += 32*MW) sb2[i] = g_b2[i];
    }
    __syncthreads();

    const int w = tid >> 5;
    const int lane = tid & 31;
    const int gs = g_perm[blockIdx.x * MW + w];   // cnt-sorted centroid id
    const int b = gs >> 10;
    const int cnt = g_cnt[gs];

    float* gft   = sm + O_GFT + w*384;
    float* h1row = sm + O_H1  + w*128;
    float* h2row = sm + O_H2  + w*128;

    const float cx = g_cent[(size_t)gs*3+0];
    const float cy = g_cent[(size_t)gs*3+1];
    const float cz = g_cent[(size_t)gs*3+2];

    // gather neighbor features up front
    {
        const int* gi = g_gi + (size_t)gs*KK;
        for (int t = lane; t < cnt*6; t += 32) {
            int k = t / 6, i = t - 6*k;
            int idx = gi[k];
            float v;
            if (i < 3) v = xyz[((size_t)b*3 + i)*NN + idx] - (i==0 ? cx : (i==1 ? cy : cz));
            else       v = pts[((size_t)b*3 + (i-3))*NN + idx];
            gft[t] = v;
        }
        if (cnt < KK && lane < 6) gft[cnt*6 + lane] = 0.0f;  // pad slot for odd cnt
    }

    const int cA = lane, cB = lane + 32;
    float w0A[6], w0B[6];
#pragma unroll
    for (int i = 0; i < 6; i++) { w0A[i] = g_w0[cA*6+i]; w0B[i] = g_w0[cB*6+i]; }
    const float b0A = g_b0[cA], b0B = g_b0[cB];
    const float b1A = sb1[cA],  b1B = sb1[cB];
    const float4 b2v = *(const float4*)&sb2[4*lane];

    float m0 = 0.f, m1 = 0.f, m2 = 0.f, m3 = 0.f;
    __syncwarp();

    for (int k = 0; k < cnt; k += 2) {
        // ---- layer 1, neighbors A=k, B=k+1 ----
        const float* fA = gft + k*6;
        const float* fB = fA + 6;
        {
            float a0 = b0A, a1 = b0B, a2 = b0A, a3 = b0B;
#pragma unroll
            for (int i = 0; i < 6; i++) {
                a0 += w0A[i]*fA[i]; a1 += w0B[i]*fA[i];
                a2 += w0A[i]*fB[i]; a3 += w0B[i]*fB[i];
            }
            h1row[cA]    = fmaxf(a0, 0.f);
            h1row[cB]    = fmaxf(a1, 0.f);
            h1row[64+cA] = fmaxf(a2, 0.f);
            h1row[64+cB] = fmaxf(a3, 0.f);
        }
        __syncwarp();

        // ---- layer 2 (weight loads shared between the 2 neighbors) ----
        float pA0 = b1A, pB0 = b1B, pA1 = b1A, pB1 = b1B;
        {
            const float4* hv = (const float4*)h1row;
#pragma unroll
            for (int c4 = 0; c4 < 16; c4++) {
                float4 ha = hv[c4];
                float4 hb = hv[16 + c4];
                const float* w1r = sw1t + c4*256;
                float a0 = w1r[cA],     a1 = w1r[64+cA], a2 = w1r[128+cA], a3 = w1r[192+cA];
                float bq0 = w1r[cB],    bq1 = w1r[64+cB], bq2 = w1r[128+cB], bq3 = w1r[192+cB];
                pA0 += a0*ha.x + a1*ha.y + a2*ha.z + a3*ha.w;
                pB0 += bq0*ha.x + bq1*ha.y + bq2*ha.z + bq3*ha.w;
                pA1 += a0*hb.x + a1*hb.y + a2*hb.z + a3*hb.w;
                pB1 += bq0*hb.x + bq1*hb.y + bq2*hb.z + bq3*hb.w;
            }
        }
        h2row[cA]    = fmaxf(pA0, 0.f);
        h2row[cB]    = fmaxf(pB0, 0.f);
        h2row[64+cA] = fmaxf(pA1, 0.f);
        h2row[64+cB] = fmaxf(pB1, 0.f);
        __syncwarp();

        // ---- layer 3 + running max (weight loads shared) ----
        float qa0=0.f,qa1=0.f,qa2=0.f,qa3=0.f;
        float qb0=0.f,qb1=0.f,qb2=0.f,qb3=0.f;
        {
            const float4* h2v = (const float4*)h2row;
#pragma unroll
            for (int c4 = 0; c4 < 16; c4++) {
                float4 ha = h2v[c4];
                float4 hb = h2v[16 + c4];
                const float* w2r = sw2t + c4*512;
                float4 wa = *(const float4*)(w2r +        4*lane);
                qa0 += wa.x*ha.x; qa1 += wa.y*ha.x; qa2 += wa.z*ha.x; qa3 += wa.w*ha.x;
                qb0 += wa.x*hb.x; qb1 += wa.y*hb.x; qb2 += wa.z*hb.x; qb3 += wa.w*hb.x;
                float4 wb = *(const float4*)(w2r + 128 + 4*lane);
                qa0 += wb.x*ha.y; qa1 += wb.y*ha.y; qa2 += wb.z*ha.y; qa3 += wb.w*ha.y;
                qb0 += wb.x*hb.y; qb1 += wb.y*hb.y; qb2 += wb.z*hb.y; qb3 += wb.w*hb.y;
                float4 wc = *(const float4*)(w2r + 256 + 4*lane);
                qa0 += wc.x*ha.z; qa1 += wc.y*ha.z; qa2 += wc.z*ha.z; qa3 += wc.w*ha.z;
                qb0 += wc.x*hb.z; qb1 += wc.y*hb.z; qb2 += wc.z*hb.z; qb3 += wc.w*hb.z;
                float4 wd = *(const float4*)(w2r + 384 + 4*lane);
                qa0 += wd.x*ha.w; qa1 += wd.y*ha.w; qa2 += wd.z*ha.w; qa3 += wd.w*ha.w;
                qb0 += wd.x*hb.w; qb1 += wd.y*hb.w; qb2 += wd.z*hb.w; qb3 += wd.w*hb.w;
            }
        }
        m0 = fmaxf(m0, fmaxf(b2v.x + qa0, 0.f));
        m1 = fmaxf(m1, fmaxf(b2v.y + qa1, 0.f));
        m2 = fmaxf(m2, fmaxf(b2v.z + qa2, 0.f));
        m3 = fmaxf(m3, fmaxf(b2v.w + qa3, 0.f));
        if (k + 1 < cnt) {  // neighbor B valid
            m0 = fmaxf(m0, fmaxf(b2v.x + qb0, 0.f));
            m1 = fmaxf(m1, fmaxf(b2v.y + qb1, 0.f));
            m2 = fmaxf(m2, fmaxf(b2v.z + qb2, 0.f));
            m3 = fmaxf(m3, fmaxf(b2v.w + qb3, 0.f));
        }
        __syncwarp();
    }

    // per-warp output (centroids are permuted -> scattered column writes)
    {
        int so = gs & 1023;
        float* dst = out + OUT_PTS_OFF + (size_t)(gs >> 10) * 128 * SS + so;
        dst[(4*lane+0)*SS] = m0;
        dst[(4*lane+1)*SS] = m1;
        dst[(4*lane+2)*SS] = m2;
        dst[(4*lane+3)*SS] = m3;
    }
}

// ---------------- launch ----------------
extern "C" void kernel_launch(void* const* d_in, const int* in_sizes, int n_in,
                              void* d_out, int out_size)
{
    const float* xyz  = (const float*)d_in[0];
    const float* pts  = (const float*)d_in[1];
    const int*   seed = (const int*)d_in[2];
    float* out = (float*)d_out;

    fold_kernel<<<1, 128>>>(
        (const float*)d_in[3],  (const float*)d_in[4],  (const float*)d_in[5],
        (const float*)d_in[6],  (const float*)d_in[7],  (const float*)d_in[8],
        (const float*)d_in[9],  (const float*)d_in[10], (const float*)d_in[11],
        (const float*)d_in[12], (const float*)d_in[13], (const float*)d_in[14],
        (const float*)d_in[15], (const float*)d_in[16], (const float*)d_in[17],
        (const float*)d_in[18], (const float*)d_in[19], (const float*)d_in[20]);

    cudaFuncSetAttribute(fps_kernel, cudaFuncAttributeMaxDynamicSharedMemorySize,
                         3*NN*sizeof(float));
    fps_kernel<<<BB*8, 256, 3*NN*sizeof(float)>>>(xyz, seed, out);

    ballq_kernel<<<(BB*SS)/8, 256>>>(xyz);
    sortc_kernel<<<1, 1024>>>();

    cudaFuncSetAttribute(mlp_kernel, cudaFuncAttributeMaxDynamicSharedMemorySize,
                         SMEMF * sizeof(float));
    mlp_kernel<<<(BB*SS)/MW, 32*MW, SMEMF * sizeof(float)>>>(xyz, pts, out);
}